// round 4
// baseline (speedup 1.0000x reference)
#include <cuda_runtime.h>
#include <cuda_fp16.h>

// ---------------- problem constants ----------------
#define Bn    32
#define Hh    56
#define Wd    56
#define Cc    128
#define NHh   4
#define HDd   32
#define NKk   245      // 7*35 keys per window
#define NQq   49       // 7*7 queries per window
#define SCALE 0.17677669529663687f   // 32^-0.5

// ---------------- smem layout (float offsets) ----------------
// Phase 1: Q [0..1568) stride 32 (plain), K [1568..9408) stride 32 (XOR-swizzled)
// Phase 2 overlay (same region, after QK^T register GEMM completes):
//   attn fp16 : 49 rows x 248 halves (row stride 248 halves = 496B) = floats [0..6076)
//   partials  : 49 x 35 at 6080
//   row_max   : 49 at 7800
//   row_sum   : 49 at 7856
// V: [9408..17592), 248 rows x 33 (rows 245..247 zeroed)
#define OFF_Q    0
#define OFF_K    1568
#define OFF_PM   6080
#define OFF_RM   7800
#define OFF_RS   7856
#define OFF_V    9408
#define SMEM_FLOATS 17592
#define SMEM_BYTES (SMEM_FLOATS * 4)   // 70,368 B -> 3 CTAs/SM

__global__ __launch_bounds__(256, 3)
void lepe_attn_kernel(const float* __restrict__ qkv,
                      const float* __restrict__ w_lepe,
                      const float* __restrict__ b_lepe,
                      float* __restrict__ out)
{
    extern __shared__ float sm[];

    const int bid = blockIdx.x;
    const int h   = bid & 3;
    const int pw  = (bid >> 2) & 7;
    const int ph  = (bid >> 5) & 7;
    const int b   = bid >> 8;
    const int tid = threadIdx.x;

    const size_t plane = (size_t)Hh * Wd * Cc;          // 401408
    const float* qg = qkv + (size_t)b * plane;
    const float* kg = qkv + (size_t)Bn * plane     + (size_t)b * plane;
    const float* vg = qkv + (size_t)2 * Bn * plane + (size_t)b * plane;
    const int cbase = h * HDd;

    // -------- load q (scaled), stride 32, no swizzle (reads are broadcast) ----
    for (int idx = tid; idx < NQq * 8; idx += 256) {
        int r  = idx >> 3;
        int dv = (idx & 7) << 2;
        int qi = r / 7, qj = r - 7 * (r / 7);
        int pix = (ph * 7 + qi) * Wd + pw * 7 + qj;
        float4 val = *(const float4*)(qg + (size_t)pix * Cc + cbase + dv);
        val.x *= SCALE; val.y *= SCALE; val.z *= SCALE; val.w *= SCALE;
        *(float4*)(sm + OFF_Q + r * 32 + dv) = val;
    }

    // -------- load k (swizzled stride 32) and v (stride 33, rows 245..247 zero) ----
    for (int idx = tid; idx < 248 * 8; idx += 256) {
        int kk = idx >> 3;
        int g  = idx & 7;          // 16B granule within row
        int ky = kk / 35, kx = kk - 35 * (kk / 35);
        int x = pw * 7 + kx - 14;
        int y = ph * 7 + ky;
        float4 kv = make_float4(0.f, 0.f, 0.f, 0.f);
        float4 vv = make_float4(0.f, 0.f, 0.f, 0.f);
        if (kk < NKk && x >= 0 && x < Wd) {
            size_t gidx = (size_t)(y * Wd + x) * Cc + cbase + (g << 2);
            kv = *(const float4*)(kg + gidx);
            vv = *(const float4*)(vg + gidx);
        }
        if (kk < NKk) {
            int gs = g ^ (kk & 7);  // XOR swizzle -> conflict-free LDS.128 later
            *(float4*)(sm + OFF_K + kk * 32 + (gs << 2)) = kv;
        }
        float* vd = sm + OFF_V + kk * 33 + (g << 2);
        vd[0] = vv.x; vd[1] = vv.y; vd[2] = vv.z; vd[3] = vv.w;
    }
    __syncthreads();

    // -------- QK^T in registers: 49 x 245, grid 7x35, 7x7 tile, float4 k-steps ----
    float acc[7][7];
    int tr = 0, tc = 0;
    if (tid < NKk) {
        tr = tid / 35;
        tc = tid - 35 * tr;
        #pragma unroll
        for (int i = 0; i < 7; i++)
            #pragma unroll
            for (int j = 0; j < 7; j++) acc[i][j] = 0.f;

        int kbase[7], kpar[7];
        #pragma unroll
        for (int j = 0; j < 7; j++) {
            int row = tc + 35 * j;
            kbase[j] = OFF_K + row * 32;
            kpar[j]  = row & 7;
        }
        const float* qb = sm + OFF_Q + tr * 32;   // row tr+7i at qb + i*224

        #pragma unroll 2
        for (int kk4 = 0; kk4 < 8; kk4++) {
            // j = 0..3
            float4 b0 = *(const float4*)(sm + kbase[0] + ((kk4 ^ kpar[0]) << 2));
            float4 b1 = *(const float4*)(sm + kbase[1] + ((kk4 ^ kpar[1]) << 2));
            float4 b2 = *(const float4*)(sm + kbase[2] + ((kk4 ^ kpar[2]) << 2));
            float4 b3 = *(const float4*)(sm + kbase[3] + ((kk4 ^ kpar[3]) << 2));
            #pragma unroll
            for (int i = 0; i < 7; i++) {
                float4 a = *(const float4*)(qb + i * 224 + (kk4 << 2));
                acc[i][0] = fmaf(a.x,b0.x,fmaf(a.y,b0.y,fmaf(a.z,b0.z,fmaf(a.w,b0.w,acc[i][0]))));
                acc[i][1] = fmaf(a.x,b1.x,fmaf(a.y,b1.y,fmaf(a.z,b1.z,fmaf(a.w,b1.w,acc[i][1]))));
                acc[i][2] = fmaf(a.x,b2.x,fmaf(a.y,b2.y,fmaf(a.z,b2.z,fmaf(a.w,b2.w,acc[i][2]))));
                acc[i][3] = fmaf(a.x,b3.x,fmaf(a.y,b3.y,fmaf(a.z,b3.z,fmaf(a.w,b3.w,acc[i][3]))));
            }
            // j = 4..6
            float4 b4 = *(const float4*)(sm + kbase[4] + ((kk4 ^ kpar[4]) << 2));
            float4 b5 = *(const float4*)(sm + kbase[5] + ((kk4 ^ kpar[5]) << 2));
            float4 b6 = *(const float4*)(sm + kbase[6] + ((kk4 ^ kpar[6]) << 2));
            #pragma unroll
            for (int i = 0; i < 7; i++) {
                float4 a = *(const float4*)(qb + i * 224 + (kk4 << 2));
                acc[i][4] = fmaf(a.x,b4.x,fmaf(a.y,b4.y,fmaf(a.z,b4.z,fmaf(a.w,b4.w,acc[i][4]))));
                acc[i][5] = fmaf(a.x,b5.x,fmaf(a.y,b5.y,fmaf(a.z,b5.z,fmaf(a.w,b5.w,acc[i][5]))));
                acc[i][6] = fmaf(a.x,b6.x,fmaf(a.y,b6.y,fmaf(a.z,b6.z,fmaf(a.w,b6.w,acc[i][6]))));
            }
        }
    }
    __syncthreads();   // Q/K reads done -> region becomes attn fp16 + partials

    // -------- step 1: per-thread row-local max -> partials; zero pad cols ----
    if (tid < NKk) {
        #pragma unroll
        for (int i = 0; i < 7; i++) {
            float lm = acc[i][0];
            #pragma unroll
            for (int j = 1; j < 7; j++) lm = fmaxf(lm, acc[i][j]);
            sm[OFF_PM + (tr + 7 * i) * 35 + tc] = lm;
        }
    }
    if (tid < NQq) {   // zero attn cols 245..247 (k-loop tail)
        __half* hp = (__half*)sm + tid * 248;
        hp[245] = __float2half(0.f); hp[246] = __float2half(0.f); hp[247] = __float2half(0.f);
    }
    __syncthreads();

    // -------- step 2: row max over 35 partials --------
    if (tid < NQq) {
        const float* p = sm + OFF_PM + tid * 35;
        float m = p[0];
        #pragma unroll
        for (int u = 1; u < 35; u++) m = fmaxf(m, p[u]);
        sm[OFF_RM + tid] = m;
    }
    __syncthreads();

    // -------- step 3: exp, write attn fp16 straight from registers ----------
    if (tid < NKk) {
        #pragma unroll
        for (int i = 0; i < 7; i++) {
            const int row = tr + 7 * i;
            const float rm = sm[OFF_RM + row];
            __half* hrow = (__half*)sm + row * 248;
            float lsum = 0.f;
            #pragma unroll
            for (int j = 0; j < 7; j++) {
                float e = __expf(acc[i][j] - rm);
                lsum += e;
                hrow[tc + 35 * j] = __float2half_rn(e);
            }
            sm[OFF_PM + row * 35 + tc] = lsum;
        }
    }
    __syncthreads();

    // -------- step 4: row sum over 35 partials --------
    if (tid < NQq) {
        const float* p = sm + OFF_PM + tid * 35;
        float s = 0.f;
        #pragma unroll
        for (int u = 0; u < 35; u++) s += p[u];
        sm[OFF_RS + tid] = s;
    }
    __syncthreads();

    // -------- out = attn(fp16) @ v (k-step 8) + LePE, store -------------------
    if (tid < 224) {
        const int wr = tid >> 5;     // qj (column within window)
        const int td = tid & 31;     // head-dim lane
        float oacc[7];
        #pragma unroll
        for (int i = 0; i < 7; i++) oacc[i] = 0.f;

        #pragma unroll 2
        for (int k8 = 0; k8 < 31; k8++) {
            const int k = k8 * 8;
            float vv[8];
            #pragma unroll
            for (int u = 0; u < 8; u++) vv[u] = sm[OFF_V + (k + u) * 33 + td];
            #pragma unroll
            for (int i = 0; i < 7; i++) {
                float4 raw = *(const float4*)((const __half*)sm + (wr + 7 * i) * 248 + k);
                const __half2* hp = (const __half2*)&raw;
                float2 f0 = __half22float2(hp[0]);
                float2 f1 = __half22float2(hp[1]);
                float2 f2 = __half22float2(hp[2]);
                float2 f3 = __half22float2(hp[3]);
                oacc[i] = fmaf(f0.x, vv[0], oacc[i]);
                oacc[i] = fmaf(f0.y, vv[1], oacc[i]);
                oacc[i] = fmaf(f1.x, vv[2], oacc[i]);
                oacc[i] = fmaf(f1.y, vv[3], oacc[i]);
                oacc[i] = fmaf(f2.x, vv[4], oacc[i]);
                oacc[i] = fmaf(f2.y, vv[5], oacc[i]);
                oacc[i] = fmaf(f3.x, vv[6], oacc[i]);
                oacc[i] = fmaf(f3.y, vv[7], oacc[i]);
            }
        }

        // LePE weights for this channel
        const int c = cbase + td;
        const float bl = b_lepe[c];
        float wl[9];
        #pragma unroll
        for (int w9 = 0; w9 < 9; w9++) wl[w9] = w_lepe[w9 * Cc + c];

        const int qj = wr;
        #pragma unroll
        for (int i = 0; i < 7; i++) {           // qi = i, row r = i*7 + qj
            const int r = qj + 7 * i;
            float o = oacc[i] / sm[OFF_RS + r];

            // depthwise 3x3 on the 7x7 window-center V tile (zero pad at edges)
            float l = bl;
            #pragma unroll
            for (int di = -1; di <= 1; di++) {
                const int yy = i + di;
                if (yy < 0 || yy >= 7) continue;
                #pragma unroll
                for (int dj = -1; dj <= 1; dj++) {
                    const int xx = qj + dj;
                    if (xx < 0 || xx >= 7) continue;
                    l = fmaf(wl[(di + 1) * 3 + (dj + 1)],
                             sm[OFF_V + (yy * 35 + 14 + xx) * 33 + td], l);
                }
            }
            o += l;

            const int pix = (ph * 7 + i) * Wd + pw * 7 + qj;
            out[(size_t)b * plane + (size_t)pix * Cc + c] = o;
        }
    }
}

extern "C" void kernel_launch(void* const* d_in, const int* in_sizes, int n_in,
                              void* d_out, int out_size)
{
    const float* qkv    = (const float*)d_in[0];
    const float* w_lepe = (const float*)d_in[1];
    const float* b_lepe = (const float*)d_in[2];
    float* out          = (float*)d_out;

    cudaFuncSetAttribute(lepe_attn_kernel,
                         cudaFuncAttributeMaxDynamicSharedMemorySize, SMEM_BYTES);
    lepe_attn_kernel<<<Bn * 8 * 8 * NHh, 256, SMEM_BYTES>>>(qkv, w_lepe, b_lepe, out);
}

// round 5
// speedup vs baseline: 1.6123x; 1.6123x over previous
#include <cuda_runtime.h>
#include <cuda_fp16.h>
#include <cstdint>

// ---------------- problem constants ----------------
#define Bn    32
#define Wd    56
#define Cc    128
#define SCALE 0.17677669529663687f   // 32^-0.5

// MMA-padded dims: M=64 (49 queries), N=256 (245 keys), K=32 head dim
// ---------------- smem layout (4-byte word offsets) ----------------
// Phase 1:  Qs 64x36 words (tf32 bits), Ks 256x36 words (tf32 bits)
// Phase 2:  P (fp16, 64 rows x 264 halves = 64x132 words) OVERLAYS Qs+Ks
// Vt (fp16, transposed [dim][k], 32 rows x 264 halves = 32x132 words): persistent
// reductions: rowmax partials 64x8, rowmax 64, rowsum partials 64x8, rowsum 64
#define OFF_QS   0
#define OFF_KS   2304      // 64*36
#define OFF_VT   11520     // 2304 + 256*36
#define OFF_RMP  15744     // 11520 + 32*132
#define OFF_RMX  16256
#define OFF_RSP  16320
#define OFF_RSM  16832
#define SMEM_WORDS 16896
#define SMEM_BYTES (SMEM_WORDS * 4)    // 67,584 B -> 2 CTAs/SM

__device__ __forceinline__ unsigned f2tf32(float f) {
    unsigned u;
    asm("cvt.rna.tf32.f32 %0, %1;" : "=r"(u) : "f"(f));
    return u;
}

__device__ __forceinline__ void mma_tf32(float c[4], const unsigned a[4],
                                         unsigned b0, unsigned b1) {
    asm volatile(
        "mma.sync.aligned.m16n8k8.row.col.f32.tf32.tf32.f32 "
        "{%0,%1,%2,%3}, {%4,%5,%6,%7}, {%8,%9}, {%0,%1,%2,%3};"
        : "+f"(c[0]), "+f"(c[1]), "+f"(c[2]), "+f"(c[3])
        : "r"(a[0]), "r"(a[1]), "r"(a[2]), "r"(a[3]), "r"(b0), "r"(b1));
}

__device__ __forceinline__ void mma_f16(float c[4],
                                        unsigned a0, unsigned a1, unsigned a2, unsigned a3,
                                        unsigned b0, unsigned b1) {
    asm volatile(
        "mma.sync.aligned.m16n8k16.row.col.f32.f16.f16.f32 "
        "{%0,%1,%2,%3}, {%4,%5,%6,%7}, {%8,%9}, {%0,%1,%2,%3};"
        : "+f"(c[0]), "+f"(c[1]), "+f"(c[2]), "+f"(c[3])
        : "r"(a0), "r"(a1), "r"(a2), "r"(a3), "r"(b0), "r"(b1));
}

__global__ __launch_bounds__(256, 2)
void lepe_attn_kernel(const float* __restrict__ qkv,
                      const float* __restrict__ w_lepe,
                      const float* __restrict__ b_lepe,
                      float* __restrict__ out)
{
    extern __shared__ float smf[];
    unsigned* smu = (unsigned*)smf;

    const int bid = blockIdx.x;
    const int h   = bid & 3;
    const int pw  = (bid >> 2) & 7;
    const int ph  = (bid >> 5) & 7;
    const int b   = bid >> 8;
    const int tid = threadIdx.x;
    const int w   = tid >> 5;
    const int lane = tid & 31;
    const int g   = lane >> 2;   // group id (0..7)
    const int t   = lane & 3;    // thread-in-group

    const size_t plane = (size_t)Wd * Wd * Cc;          // 56*56*128
    const float* qg = qkv + (size_t)b * plane;
    const float* kg = qkv + (size_t)Bn * plane     + (size_t)b * plane;
    const float* vg = qkv + (size_t)2 * Bn * plane + (size_t)b * plane;
    const int cbase = h * 32;

    // ================= load phase =================
    // Q -> Qs (tf32 bits, scaled), rows 49..63 zero. stride 36 words.
    for (int idx = tid; idx < 64 * 8; idx += 256) {
        int r  = idx >> 3;
        int dv = (idx & 7) << 2;
        uint4 st = make_uint4(0u, 0u, 0u, 0u);
        if (r < 49) {
            int qi = r / 7, qj = r - 7 * (r / 7);
            int pix = (ph * 7 + qi) * Wd + pw * 7 + qj;
            float4 v = *(const float4*)(qg + (size_t)pix * Cc + cbase + dv);
            st.x = f2tf32(v.x * SCALE); st.y = f2tf32(v.y * SCALE);
            st.z = f2tf32(v.z * SCALE); st.w = f2tf32(v.w * SCALE);
        }
        *(uint4*)(smu + OFF_QS + r * 36 + dv) = st;
    }
    // K -> Ks (tf32 bits), rows 245..255 zero;  V -> Vt (fp16, transposed)
    for (int idx = tid; idx < 256 * 8; idx += 256) {
        int kk = idx >> 3;
        int dv = (idx & 7) << 2;
        float4 kv = make_float4(0.f, 0.f, 0.f, 0.f);
        float4 vv = make_float4(0.f, 0.f, 0.f, 0.f);
        bool real = (kk < 245);
        if (real) {
            int ky = kk / 35, kx = kk - 35 * (kk / 35);
            int x = pw * 7 + kx - 14;
            int y = ph * 7 + ky;
            if (x >= 0 && x < Wd) {
                size_t gi = (size_t)(y * Wd + x) * Cc + cbase + dv;
                kv = *(const float4*)(kg + gi);
                vv = *(const float4*)(vg + gi);
            }
        }
        uint4 ks4;
        ks4.x = f2tf32(kv.x); ks4.y = f2tf32(kv.y);
        ks4.z = f2tf32(kv.z); ks4.w = f2tf32(kv.w);
        *(uint4*)(smu + OFF_KS + kk * 36 + dv) = ks4;
        if (real) {
            __half* hv = (__half*)(smu + OFF_VT);
            hv[(dv + 0) * 264 + kk] = __float2half_rn(vv.x);
            hv[(dv + 1) * 264 + kk] = __float2half_rn(vv.y);
            hv[(dv + 2) * 264 + kk] = __float2half_rn(vv.z);
            hv[(dv + 3) * 264 + kk] = __float2half_rn(vv.w);
        }
    }
    // zero Vt pad k in [245,256)
    for (int idx = tid; idx < 32 * 11; idx += 256) {
        int d = idx / 11, k = 245 + idx - 11 * (idx / 11);
        ((__half*)(smu + OFF_VT))[d * 264 + k] = __float2half(0.f);
    }
    __syncthreads();

    // ================= QK^T: m16n8k8 tf32 =================
    // warp w owns N-strip [w*32, w*32+32): 4 m-tiles x 4 n-tiles
    float acc[4][4][4];
    #pragma unroll
    for (int mt = 0; mt < 4; mt++)
        #pragma unroll
        for (int nt = 0; nt < 4; nt++)
            #pragma unroll
            for (int e = 0; e < 4; e++) acc[mt][nt][e] = 0.f;

    {
        const unsigned* QsU = smu + OFF_QS;
        const unsigned* KsU = smu + OFF_KS;
        #pragma unroll
        for (int ks = 0; ks < 4; ks++) {
            unsigned a[4][4];
            #pragma unroll
            for (int mt = 0; mt < 4; mt++) {
                int r0 = (mt * 16 + g) * 36 + ks * 8 + t;
                a[mt][0] = QsU[r0];
                a[mt][1] = QsU[r0 + 8 * 36];
                a[mt][2] = QsU[r0 + 4];
                a[mt][3] = QsU[r0 + 8 * 36 + 4];
            }
            #pragma unroll
            for (int nt = 0; nt < 4; nt++) {
                int nb = (w * 32 + nt * 8 + g) * 36 + ks * 8 + t;
                unsigned b0 = KsU[nb], b1 = KsU[nb + 4];
                #pragma unroll
                for (int mt = 0; mt < 4; mt++)
                    mma_tf32(acc[mt][nt], a[mt], b0, b1);
            }
        }
    }

    // ================= softmax on fragments =================
    // rows owned by this thread: mt*16+g (elems 0,1) and mt*16+8+g (elems 2,3)
    float rm[8];
    #pragma unroll
    for (int mt = 0; mt < 4; mt++) {
        float lo = -1e30f, hi = -1e30f;
        #pragma unroll
        for (int nt = 0; nt < 4; nt++) {
            lo = fmaxf(lo, fmaxf(acc[mt][nt][0], acc[mt][nt][1]));
            hi = fmaxf(hi, fmaxf(acc[mt][nt][2], acc[mt][nt][3]));
        }
        rm[mt * 2] = lo; rm[mt * 2 + 1] = hi;
    }
    #pragma unroll
    for (int s = 1; s <= 2; s <<= 1)
        #pragma unroll
        for (int i = 0; i < 8; i++)
            rm[i] = fmaxf(rm[i], __shfl_xor_sync(0xffffffffu, rm[i], s));
    if (t == 0) {
        #pragma unroll
        for (int mt = 0; mt < 4; mt++) {
            smf[OFF_RMP + (mt * 16 + g) * 8 + w]     = rm[mt * 2];
            smf[OFF_RMP + (mt * 16 + 8 + g) * 8 + w] = rm[mt * 2 + 1];
        }
    }
    __syncthreads();
    if (tid < 64) {
        float m = smf[OFF_RMP + tid * 8];
        #pragma unroll
        for (int u = 1; u < 8; u++) m = fmaxf(m, smf[OFF_RMP + tid * 8 + u]);
        smf[OFF_RMX + tid] = m;
    }
    __syncthreads();

    // exp -> P (fp16, overlays Qs/Ks; all warps past both syncs => safe)
    unsigned* PU = smu;   // word 0; row stride 132 words (264 halves)
    float sums[8];
    #pragma unroll
    for (int i = 0; i < 8; i++) sums[i] = 0.f;
    #pragma unroll
    for (int mt = 0; mt < 4; mt++) {
        float m0 = smf[OFF_RMX + mt * 16 + g];
        float m1 = smf[OFF_RMX + mt * 16 + 8 + g];
        #pragma unroll
        for (int nt = 0; nt < 4; nt++) {
            int c0 = w * 32 + nt * 8 + 2 * t;
            float e00 = (c0     < 245) ? __expf(acc[mt][nt][0] - m0) : 0.f;
            float e01 = (c0 + 1 < 245) ? __expf(acc[mt][nt][1] - m0) : 0.f;
            float e10 = (c0     < 245) ? __expf(acc[mt][nt][2] - m1) : 0.f;
            float e11 = (c0 + 1 < 245) ? __expf(acc[mt][nt][3] - m1) : 0.f;
            sums[mt * 2]     += e00 + e01;
            sums[mt * 2 + 1] += e10 + e11;
            __half2 h0 = __floats2half2_rn(e00, e01);
            __half2 h1 = __floats2half2_rn(e10, e11);
            int wofs = w * 16 + nt * 4 + t;
            PU[(mt * 16 + g) * 132 + wofs]     = *(unsigned*)&h0;
            PU[(mt * 16 + 8 + g) * 132 + wofs] = *(unsigned*)&h1;
        }
    }
    #pragma unroll
    for (int s = 1; s <= 2; s <<= 1)
        #pragma unroll
        for (int i = 0; i < 8; i++)
            sums[i] += __shfl_xor_sync(0xffffffffu, sums[i], s);
    if (t == 0) {
        #pragma unroll
        for (int mt = 0; mt < 4; mt++) {
            smf[OFF_RSP + (mt * 16 + g) * 8 + w]     = sums[mt * 2];
            smf[OFF_RSP + (mt * 16 + 8 + g) * 8 + w] = sums[mt * 2 + 1];
        }
    }
    __syncthreads();
    if (tid < 64) {
        float s = 0.f;
        #pragma unroll
        for (int u = 0; u < 8; u++) s += smf[OFF_RSP + tid * 8 + u];
        smf[OFF_RSM + tid] = s;
    }

    // ================= P @ V: m16n8k16 f16 =================
    // 16 output tiles (4 mt x 4 nt-of-8); warp w gets tiles 2w, 2w+1 (share nt)
    const int mt0 = (w * 2) & 3;
    const int mt1 = (w * 2 + 1) & 3;
    const int ntv = (w * 2) >> 2;
    float pa[2][4];
    #pragma unroll
    for (int e = 0; e < 4; e++) { pa[0][e] = 0.f; pa[1][e] = 0.f; }
    {
        const unsigned* VtU = smu + OFF_VT;
        #pragma unroll
        for (int ks = 0; ks < 16; ks++) {
            int nb = (ntv * 8 + g) * 132 + ks * 8 + t;
            unsigned b0 = VtU[nb], b1 = VtU[nb + 4];
            int r0 = (mt0 * 16 + g) * 132 + ks * 8 + t;
            mma_f16(pa[0], PU[r0], PU[r0 + 8 * 132], PU[r0 + 4], PU[r0 + 8 * 132 + 4], b0, b1);
            int r1 = (mt1 * 16 + g) * 132 + ks * 8 + t;
            mma_f16(pa[1], PU[r1], PU[r1 + 8 * 132], PU[r1 + 4], PU[r1 + 8 * 132 + 4], b0, b1);
        }
    }
    __syncthreads();   // rowsum final visible

    // ================= epilogue: normalize + LePE + store =================
    {
        const int c0  = ntv * 8 + 2 * t;       // head-dim cols c0, c0+1
        const int ch0 = cbase + c0;
        const float bl0 = b_lepe[ch0], bl1 = b_lepe[ch0 + 1];
        float wl0[9], wl1[9];
        #pragma unroll
        for (int i = 0; i < 9; i++) {
            wl0[i] = w_lepe[i * Cc + ch0];
            wl1[i] = w_lepe[i * Cc + ch0 + 1];
        }
        const __half* hv = (const __half*)(smu + OFF_VT);
        #pragma unroll
        for (int pi = 0; pi < 2; pi++) {
            const int mt = pi ? mt1 : mt0;
            #pragma unroll
            for (int hh = 0; hh < 2; hh++) {
                int row = mt * 16 + hh * 8 + g;
                if (row >= 49) continue;
                float inv = 1.0f / smf[OFF_RSM + row];
                float o0 = pa[pi][hh * 2 + 0] * inv;
                float o1 = pa[pi][hh * 2 + 1] * inv;
                int qi = row / 7, qj = row - 7 * (row / 7);
                float l0 = bl0, l1 = bl1;
                #pragma unroll
                for (int di = -1; di <= 1; di++) {
                    int yy = qi + di;
                    if (yy < 0 || yy >= 7) continue;
                    #pragma unroll
                    for (int dj = -1; dj <= 1; dj++) {
                        int xx = qj + dj;
                        if (xx < 0 || xx >= 7) continue;
                        int kkk = yy * 35 + 14 + xx;
                        float wv0 = wl0[(di + 1) * 3 + dj + 1];
                        float wv1 = wl1[(di + 1) * 3 + dj + 1];
                        l0 = fmaf(wv0, __half2float(hv[c0 * 264 + kkk]), l0);
                        l1 = fmaf(wv1, __half2float(hv[(c0 + 1) * 264 + kkk]), l1);
                    }
                }
                int pix = (ph * 7 + qi) * Wd + pw * 7 + qj;
                float2 o = make_float2(o0 + l0, o1 + l1);
                *(float2*)(out + (size_t)b * plane + (size_t)pix * Cc + ch0) = o;
            }
        }
    }
}

extern "C" void kernel_launch(void* const* d_in, const int* in_sizes, int n_in,
                              void* d_out, int out_size)
{
    const float* qkv    = (const float*)d_in[0];
    const float* w_lepe = (const float*)d_in[1];
    const float* b_lepe = (const float*)d_in[2];
    float* out          = (float*)d_out;

    cudaFuncSetAttribute(lepe_attn_kernel,
                         cudaFuncAttributeMaxDynamicSharedMemorySize, SMEM_BYTES);
    lepe_attn_kernel<<<Bn * 8 * 8 * 4, 256, SMEM_BYTES>>>(qkv, w_lepe, b_lepe, out);
}

// round 6
// speedup vs baseline: 1.7045x; 1.0572x over previous
#include <cuda_runtime.h>
#include <cuda_fp16.h>
#include <cstdint>

// ---------------- problem constants ----------------
#define Bn    32
#define Wd    56
#define Cc    128
#define SCALE 0.17677669529663687f   // 32^-0.5

// MMA dims: M=64 (49 q), N=256 (245 k), K=32 head dim. All operands fp16.
// ---------------- smem layout (4-byte word offsets) ----------------
// Phase 1: Qh 64 rows x 40 halves (20 words), Kh 256 rows x 40 halves
// Phase 2: P fp16 64 rows x 264 halves (132 words) OVERLAYS Qh+Kh
// Vt fp16 [dim][key] 32 rows x 264 halves: persistent
#define OFF_Q    0          // 64*20   = 1280 words
#define OFF_K    1280       // 256*20  = 5120 -> ends 6400
#define OFF_P    0          // 64*132  = 8448 words (overlay)
#define OFF_VT   8448       // 32*132  = 4224 -> ends 12672
#define OFF_RMP  12672      // 64*8
#define OFF_RMX  13184      // 64
#define OFF_RSP  13248      // 64*8
#define OFF_RSM  13760      // 64
#define SMEM_WORDS 13824
#define SMEM_BYTES (SMEM_WORDS * 4)   // 55,296 B -> 2 CTAs/SM, big L1 left

__device__ __forceinline__ void ldsm_x4(unsigned r[4], const void* p) {
    unsigned a = (unsigned)__cvta_generic_to_shared(p);
    asm volatile("ldmatrix.sync.aligned.m8n8.x4.shared.b16 {%0,%1,%2,%3}, [%4];"
        : "=r"(r[0]), "=r"(r[1]), "=r"(r[2]), "=r"(r[3]) : "r"(a));
}

__device__ __forceinline__ void mma_f16(float c[4],
                                        unsigned a0, unsigned a1, unsigned a2, unsigned a3,
                                        unsigned b0, unsigned b1) {
    asm volatile(
        "mma.sync.aligned.m16n8k16.row.col.f32.f16.f16.f32 "
        "{%0,%1,%2,%3}, {%4,%5,%6,%7}, {%8,%9}, {%0,%1,%2,%3};"
        : "+f"(c[0]), "+f"(c[1]), "+f"(c[2]), "+f"(c[3])
        : "r"(a0), "r"(a1), "r"(a2), "r"(a3), "r"(b0), "r"(b1));
}

__global__ __launch_bounds__(256, 2)
void lepe_attn_kernel(const float* __restrict__ qkv,
                      const float* __restrict__ w_lepe,
                      const float* __restrict__ b_lepe,
                      float* __restrict__ out)
{
    extern __shared__ float smf[];
    unsigned* smu = (unsigned*)smf;
    __half*   smh = (__half*)smf;

    const int bid = blockIdx.x;
    const int h   = bid & 3;
    const int pw  = (bid >> 2) & 7;
    const int ph  = (bid >> 5) & 7;
    const int b   = bid >> 8;
    const int tid = threadIdx.x;
    const int w   = tid >> 5;
    const int lane = tid & 31;
    const int g   = lane >> 2;
    const int t   = lane & 3;

    const size_t plane = (size_t)Wd * Wd * Cc;
    const float* qg = qkv + (size_t)b * plane;
    const float* kg = qkv + (size_t)Bn * plane     + (size_t)b * plane;
    const float* vg = qkv + (size_t)2 * Bn * plane + (size_t)b * plane;
    const int cbase = h * 32;

    // ================= load phase =================
    // Q -> fp16 (scaled), rows 49..63 zero; row stride 40 halves
    for (int idx = tid; idx < 64 * 8; idx += 256) {
        int r  = idx >> 3;
        int dv = (idx & 7) << 2;
        __half2 h01 = __floats2half2_rn(0.f, 0.f), h23 = h01;
        if (r < 49) {
            int qi = r / 7, qj = r - 7 * (r / 7);
            int pix = (ph * 7 + qi) * Wd + pw * 7 + qj;
            float4 v = *(const float4*)(qg + (size_t)pix * Cc + cbase + dv);
            h01 = __floats2half2_rn(v.x * SCALE, v.y * SCALE);
            h23 = __floats2half2_rn(v.z * SCALE, v.w * SCALE);
        }
        uint2 st = make_uint2(*(unsigned*)&h01, *(unsigned*)&h23);
        *(uint2*)(smh + OFF_Q * 2 + r * 40 + dv) = st;
    }
    // K -> fp16 rows 245..255 zero; V -> Vt fp16 transposed [dim][key] stride 264
    for (int idx = tid; idx < 256 * 8; idx += 256) {
        int kk = idx >> 3;
        int dv = (idx & 7) << 2;
        float4 kv = make_float4(0.f, 0.f, 0.f, 0.f);
        float4 vv = make_float4(0.f, 0.f, 0.f, 0.f);
        bool real = (kk < 245);
        if (real) {
            int ky = kk / 35, kx = kk - 35 * (kk / 35);
            int x = pw * 7 + kx - 14;
            int y = ph * 7 + ky;
            if (x >= 0 && x < Wd) {
                size_t gi = (size_t)(y * Wd + x) * Cc + cbase + dv;
                kv = *(const float4*)(kg + gi);
                vv = *(const float4*)(vg + gi);
            }
        }
        __half2 k01 = __floats2half2_rn(kv.x, kv.y);
        __half2 k23 = __floats2half2_rn(kv.z, kv.w);
        uint2 st = make_uint2(*(unsigned*)&k01, *(unsigned*)&k23);
        *(uint2*)(smh + OFF_K * 2 + kk * 40 + dv) = st;
        if (real) {
            __half* hv = smh + OFF_VT * 2;
            hv[(dv + 0) * 264 + kk] = __float2half_rn(vv.x);
            hv[(dv + 1) * 264 + kk] = __float2half_rn(vv.y);
            hv[(dv + 2) * 264 + kk] = __float2half_rn(vv.z);
            hv[(dv + 3) * 264 + kk] = __float2half_rn(vv.w);
        }
    }
    // zero Vt pad keys [245,264)
    for (int idx = tid; idx < 32 * 19; idx += 256) {
        int d = idx / 19, k = 245 + idx - 19 * (idx / 19);
        smh[OFF_VT * 2 + d * 264 + k] = __float2half(0.f);
    }
    __syncthreads();

    // ================= QK^T: m16n8k16 fp16, LDSM operands =================
    float acc[4][4][4];
    #pragma unroll
    for (int mt = 0; mt < 4; mt++)
        #pragma unroll
        for (int nt = 0; nt < 4; nt++)
            #pragma unroll
            for (int e = 0; e < 4; e++) acc[mt][nt][e] = 0.f;
    {
        const __half* Qh = smh + OFF_Q * 2;
        const __half* Kh = smh + OFF_K * 2;
        const int arow = lane & 15, acol = (lane >> 4) << 3;      // A-frag lane addr
        const int brow = (lane & 7) + ((lane >> 4) << 3);         // B-frag lane addr
        const int bcol = ((lane >> 3) & 1) << 3;
        #pragma unroll
        for (int ks = 0; ks < 2; ks++) {
            const int k0 = ks * 16;
            unsigned aq[4][4];
            #pragma unroll
            for (int mt = 0; mt < 4; mt++)
                ldsm_x4(aq[mt], Qh + (mt * 16 + arow) * 40 + k0 + acol);
            #pragma unroll
            for (int j = 0; j < 2; j++) {
                unsigned bk[4];
                int n0 = w * 32 + j * 16;
                ldsm_x4(bk, Kh + (n0 + brow) * 40 + k0 + bcol);
                #pragma unroll
                for (int mt = 0; mt < 4; mt++) {
                    mma_f16(acc[mt][2 * j],     aq[mt][0], aq[mt][1], aq[mt][2], aq[mt][3], bk[0], bk[1]);
                    mma_f16(acc[mt][2 * j + 1], aq[mt][0], aq[mt][1], aq[mt][2], aq[mt][3], bk[2], bk[3]);
                }
            }
        }
    }

    // ================= softmax on fragments =================
    float rm[8];
    #pragma unroll
    for (int mt = 0; mt < 4; mt++) {
        float lo = -1e30f, hi = -1e30f;
        #pragma unroll
        for (int nt = 0; nt < 4; nt++) {
            lo = fmaxf(lo, fmaxf(acc[mt][nt][0], acc[mt][nt][1]));
            hi = fmaxf(hi, fmaxf(acc[mt][nt][2], acc[mt][nt][3]));
        }
        rm[mt * 2] = lo; rm[mt * 2 + 1] = hi;
    }
    #pragma unroll
    for (int s = 1; s <= 2; s <<= 1)
        #pragma unroll
        for (int i = 0; i < 8; i++)
            rm[i] = fmaxf(rm[i], __shfl_xor_sync(0xffffffffu, rm[i], s));
    if (t == 0) {
        #pragma unroll
        for (int mt = 0; mt < 4; mt++) {
            smf[OFF_RMP + (mt * 16 + g) * 8 + w]     = rm[mt * 2];
            smf[OFF_RMP + (mt * 16 + 8 + g) * 8 + w] = rm[mt * 2 + 1];
        }
    }
    __syncthreads();
    if (tid < 64) {
        float m = smf[OFF_RMP + tid * 8];
        #pragma unroll
        for (int u = 1; u < 8; u++) m = fmaxf(m, smf[OFF_RMP + tid * 8 + u]);
        smf[OFF_RMX + tid] = m;
    }
    __syncthreads();

    // exp -> P fp16 (overlays Qh/Kh; everyone is past the syncs above)
    unsigned* PU = smu + OFF_P;     // row stride 132 words (264 halves)
    float sums[8];
    #pragma unroll
    for (int i = 0; i < 8; i++) sums[i] = 0.f;
    #pragma unroll
    for (int mt = 0; mt < 4; mt++) {
        float m0 = smf[OFF_RMX + mt * 16 + g];
        float m1 = smf[OFF_RMX + mt * 16 + 8 + g];
        #pragma unroll
        for (int nt = 0; nt < 4; nt++) {
            int c0 = w * 32 + nt * 8 + 2 * t;
            float e00 = (c0     < 245) ? __expf(acc[mt][nt][0] - m0) : 0.f;
            float e01 = (c0 + 1 < 245) ? __expf(acc[mt][nt][1] - m0) : 0.f;
            float e10 = (c0     < 245) ? __expf(acc[mt][nt][2] - m1) : 0.f;
            float e11 = (c0 + 1 < 245) ? __expf(acc[mt][nt][3] - m1) : 0.f;
            sums[mt * 2]     += e00 + e01;
            sums[mt * 2 + 1] += e10 + e11;
            __half2 h0 = __floats2half2_rn(e00, e01);
            __half2 h1 = __floats2half2_rn(e10, e11);
            int wofs = w * 16 + nt * 4 + t;
            PU[(mt * 16 + g) * 132 + wofs]     = *(unsigned*)&h0;
            PU[(mt * 16 + 8 + g) * 132 + wofs] = *(unsigned*)&h1;
        }
    }
    #pragma unroll
    for (int s = 1; s <= 2; s <<= 1)
        #pragma unroll
        for (int i = 0; i < 8; i++)
            sums[i] += __shfl_xor_sync(0xffffffffu, sums[i], s);
    if (t == 0) {
        #pragma unroll
        for (int mt = 0; mt < 4; mt++) {
            smf[OFF_RSP + (mt * 16 + g) * 8 + w]     = sums[mt * 2];
            smf[OFF_RSP + (mt * 16 + 8 + g) * 8 + w] = sums[mt * 2 + 1];
        }
    }
    __syncthreads();
    if (tid < 64) {
        float s = 0.f;
        #pragma unroll
        for (int u = 0; u < 8; u++) s += smf[OFF_RSP + tid * 8 + u];
        smf[OFF_RSM + tid] = s;
    }

    // ================= P @ V: m16n8k16 fp16, LDSM operands =================
    const int mt0 = (w * 2) & 3;
    const int mt1 = (w * 2 + 1) & 3;
    const int ntv = (w * 2) >> 2;
    float pa[2][4];
    #pragma unroll
    for (int e = 0; e < 4; e++) { pa[0][e] = 0.f; pa[1][e] = 0.f; }
    {
        const __half* Ph  = smh + OFF_P * 2;
        const __half* VtH = smh + OFF_VT * 2;
        const int arow = lane & 15, acol = (lane >> 4) << 3;
        const int vrow = ntv * 8 + (lane & 7);
        const int vcol = (lane >> 3) << 3;    // 0,8,16,24 -> two k-steps
        #pragma unroll
        for (int ks2 = 0; ks2 < 8; ks2++) {
            const int k0 = ks2 * 32;
            unsigned bv[4];
            ldsm_x4(bv, VtH + vrow * 264 + k0 + vcol);
            #pragma unroll
            for (int s = 0; s < 2; s++) {
                const int kk0 = k0 + s * 16;
                unsigned a0[4], a1[4];
                ldsm_x4(a0, Ph + (mt0 * 16 + arow) * 264 + kk0 + acol);
                ldsm_x4(a1, Ph + (mt1 * 16 + arow) * 264 + kk0 + acol);
                mma_f16(pa[0], a0[0], a0[1], a0[2], a0[3], bv[2 * s], bv[2 * s + 1]);
                mma_f16(pa[1], a1[0], a1[1], a1[2], a1[3], bv[2 * s], bv[2 * s + 1]);
            }
        }
    }
    __syncthreads();   // rowsum final visible

    // ================= epilogue: normalize + LePE + store =================
    {
        const int c0  = ntv * 8 + 2 * t;
        const int ch0 = cbase + c0;
        const float bl0 = b_lepe[ch0], bl1 = b_lepe[ch0 + 1];
        float wl0[9], wl1[9];
        #pragma unroll
        for (int i = 0; i < 9; i++) {
            wl0[i] = w_lepe[i * Cc + ch0];
            wl1[i] = w_lepe[i * Cc + ch0 + 1];
        }
        const __half* hv = smh + OFF_VT * 2;
        #pragma unroll
        for (int pi = 0; pi < 2; pi++) {
            const int mt = pi ? mt1 : mt0;
            #pragma unroll
            for (int hh = 0; hh < 2; hh++) {
                int row = mt * 16 + hh * 8 + g;
                if (row >= 49) continue;
                float inv = 1.0f / smf[OFF_RSM + row];
                float o0 = pa[pi][hh * 2 + 0] * inv;
                float o1 = pa[pi][hh * 2 + 1] * inv;
                int qi = row / 7, qj = row - 7 * (row / 7);
                float l0 = bl0, l1 = bl1;
                #pragma unroll
                for (int di = -1; di <= 1; di++) {
                    int yy = qi + di;
                    if (yy < 0 || yy >= 7) continue;
                    #pragma unroll
                    for (int dj = -1; dj <= 1; dj++) {
                        int xx = qj + dj;
                        if (xx < 0 || xx >= 7) continue;
                        int kkk = yy * 35 + 14 + xx;
                        l0 = fmaf(wl0[(di + 1) * 3 + dj + 1], __half2float(hv[c0 * 264 + kkk]), l0);
                        l1 = fmaf(wl1[(di + 1) * 3 + dj + 1], __half2float(hv[(c0 + 1) * 264 + kkk]), l1);
                    }
                }
                int pix = (ph * 7 + qi) * Wd + pw * 7 + qj;
                float2 o = make_float2(o0 + l0, o1 + l1);
                *(float2*)(out + (size_t)b * plane + (size_t)pix * Cc + ch0) = o;
            }
        }
    }
}

extern "C" void kernel_launch(void* const* d_in, const int* in_sizes, int n_in,
                              void* d_out, int out_size)
{
    const float* qkv    = (const float*)d_in[0];
    const float* w_lepe = (const float*)d_in[1];
    const float* b_lepe = (const float*)d_in[2];
    float* out          = (float*)d_out;

    cudaFuncSetAttribute(lepe_attn_kernel,
                         cudaFuncAttributeMaxDynamicSharedMemorySize, SMEM_BYTES);
    lepe_attn_kernel<<<Bn * 8 * 8 * 4, 256, SMEM_BYTES>>>(qkv, w_lepe, b_lepe, out);
}

// round 7
// speedup vs baseline: 2.0275x; 1.1895x over previous
#include <cuda_runtime.h>
#include <cuda_fp16.h>
#include <cstdint>

// ---------------- problem constants ----------------
#define Bn    32
#define Wd    56
#define Cc    128
#define SCALE 0.17677669529663687f   // 32^-0.5

// M=64 (49 q), N=256 (245 k), K=32 head dim. fp16 operands, fp32 accum.
// Warp w: m-tile mt=w&3 (rows mt*16..mt*16+16), key-half hf=w>>2 (128 keys).
// ---------------- smem layout (word offsets) ----------------
#define OFF_Q    0          // 64 rows x 40 halves  = 1280 words
#define OFF_K    1280       // 256 rows x 40 halves = 5120
#define OFF_V    6400       // 256 rows x 40 halves = 5120
#define OFF_RMP  11520      // 64 rows x 2 halves-of-N
#define OFF_RSP  11648      // 64 rows x 2
#define OFF_RED  11776      // 4 mt x 32 lanes x 20 = 2560 (PV pair reduction)
#define OFF_LEP  14336      // 49 x 32 fp32 LePE     = 1568
#define SMEM_WORDS 15936
#define SMEM_BYTES (SMEM_WORDS * 4)   // 63,744 B -> 2 CTAs/SM

__device__ __forceinline__ void ldsm_x4(unsigned r[4], const void* p) {
    unsigned a = (unsigned)__cvta_generic_to_shared(p);
    asm volatile("ldmatrix.sync.aligned.m8n8.x4.shared.b16 {%0,%1,%2,%3}, [%4];"
        : "=r"(r[0]), "=r"(r[1]), "=r"(r[2]), "=r"(r[3]) : "r"(a));
}
__device__ __forceinline__ void ldsm_x4t(unsigned r[4], const void* p) {
    unsigned a = (unsigned)__cvta_generic_to_shared(p);
    asm volatile("ldmatrix.sync.aligned.m8n8.x4.trans.shared.b16 {%0,%1,%2,%3}, [%4];"
        : "=r"(r[0]), "=r"(r[1]), "=r"(r[2]), "=r"(r[3]) : "r"(a));
}
__device__ __forceinline__ void mma_f16(float c[4],
                                        unsigned a0, unsigned a1, unsigned a2, unsigned a3,
                                        unsigned b0, unsigned b1) {
    asm volatile(
        "mma.sync.aligned.m16n8k16.row.col.f32.f16.f16.f32 "
        "{%0,%1,%2,%3}, {%4,%5,%6,%7}, {%8,%9}, {%0,%1,%2,%3};"
        : "+f"(c[0]), "+f"(c[1]), "+f"(c[2]), "+f"(c[3])
        : "r"(a0), "r"(a1), "r"(a2), "r"(a3), "r"(b0), "r"(b1));
}

__global__ __launch_bounds__(256, 2)
void lepe_attn_kernel(const float* __restrict__ qkv,
                      const float* __restrict__ w_lepe,
                      const float* __restrict__ b_lepe,
                      float* __restrict__ out)
{
    extern __shared__ float smf[];
    __half* smh = (__half*)smf;

    const int bid = blockIdx.x;
    const int h   = bid & 3;
    const int pw  = (bid >> 2) & 7;
    const int ph  = (bid >> 5) & 7;
    const int b   = bid >> 8;
    const int tid = threadIdx.x;
    const int w   = tid >> 5;
    const int lane = tid & 31;
    const int g   = lane >> 2;
    const int t   = lane & 3;
    const int mt  = w & 3;       // m-tile
    const int hf  = w >> 2;      // key half (0: keys 0..127, 1: 128..255)

    const size_t plane = (size_t)Wd * Wd * Cc;
    const float* qg = qkv + (size_t)b * plane;
    const float* kg = qkv + (size_t)Bn * plane     + (size_t)b * plane;
    const float* vg = qkv + (size_t)2 * Bn * plane + (size_t)b * plane;
    const int cbase = h * 32;

    // ================= load phase =================
    __half* Qh = smh + OFF_Q * 2;
    __half* Kh = smh + OFF_K * 2;
    __half* Vh = smh + OFF_V * 2;
    for (int idx = tid; idx < 64 * 8; idx += 256) {
        int r  = idx >> 3;
        int dv = (idx & 7) << 2;
        __half2 h01 = __floats2half2_rn(0.f, 0.f), h23 = h01;
        if (r < 49) {
            int qi = r / 7, qj = r - 7 * (r / 7);
            int pix = (ph * 7 + qi) * Wd + pw * 7 + qj;
            float4 v = *(const float4*)(qg + (size_t)pix * Cc + cbase + dv);
            h01 = __floats2half2_rn(v.x * SCALE, v.y * SCALE);
            h23 = __floats2half2_rn(v.z * SCALE, v.w * SCALE);
        }
        *(uint2*)(Qh + r * 40 + dv) = make_uint2(*(unsigned*)&h01, *(unsigned*)&h23);
    }
    for (int idx = tid; idx < 256 * 8; idx += 256) {
        int kk = idx >> 3;
        int dv = (idx & 7) << 2;
        float4 kv = make_float4(0.f, 0.f, 0.f, 0.f);
        float4 vv = make_float4(0.f, 0.f, 0.f, 0.f);
        if (kk < 245) {
            int ky = kk / 35, kx = kk - 35 * (kk / 35);
            int x = pw * 7 + kx - 14;
            int y = ph * 7 + ky;
            if (x >= 0 && x < Wd) {
                size_t gi = (size_t)(y * Wd + x) * Cc + cbase + dv;
                kv = *(const float4*)(kg + gi);
                vv = *(const float4*)(vg + gi);
            }
        }
        __half2 k01 = __floats2half2_rn(kv.x, kv.y), k23 = __floats2half2_rn(kv.z, kv.w);
        __half2 v01 = __floats2half2_rn(vv.x, vv.y), v23 = __floats2half2_rn(vv.z, vv.w);
        *(uint2*)(Kh + kk * 40 + dv) = make_uint2(*(unsigned*)&k01, *(unsigned*)&k23);
        *(uint2*)(Vh + kk * 40 + dv) = make_uint2(*(unsigned*)&v01, *(unsigned*)&v23);
    }
    __syncthreads();   // (1)

    // ================= QK^T: warp = (mt, key-half), 32 HMMA =================
    const int arow = lane & 15, acol = (lane >> 4) << 3;
    const int brow = (lane & 7) + ((lane >> 4) << 3);
    const int bcol = ((lane >> 3) & 1) << 3;
    unsigned aq[2][4];
    ldsm_x4(aq[0], Qh + (mt * 16 + arow) * 40 + acol);
    ldsm_x4(aq[1], Qh + (mt * 16 + arow) * 40 + 16 + acol);

    float acc[16][4];
    #pragma unroll
    for (int nt = 0; nt < 16; nt++)
        #pragma unroll
        for (int e = 0; e < 4; e++) acc[nt][e] = 0.f;

    #pragma unroll
    for (int j = 0; j < 8; j++) {
        int n0 = hf * 128 + j * 16;
        #pragma unroll
        for (int ks = 0; ks < 2; ks++) {
            unsigned bk[4];
            ldsm_x4(bk, Kh + (n0 + brow) * 40 + ks * 16 + bcol);
            mma_f16(acc[2 * j],     aq[ks][0], aq[ks][1], aq[ks][2], aq[ks][3], bk[0], bk[1]);
            mma_f16(acc[2 * j + 1], aq[ks][0], aq[ks][1], aq[ks][2], aq[ks][3], bk[2], bk[3]);
        }
    }

    // ================= softmax: quad shuffle + 2-warp combine =================
    const int r0 = mt * 16 + g, r1 = r0 + 8;
    float rm0 = -1e30f, rm1 = -1e30f;
    #pragma unroll
    for (int nt = 0; nt < 16; nt++) {
        rm0 = fmaxf(rm0, fmaxf(acc[nt][0], acc[nt][1]));
        rm1 = fmaxf(rm1, fmaxf(acc[nt][2], acc[nt][3]));
    }
    #pragma unroll
    for (int s = 1; s <= 2; s <<= 1) {
        rm0 = fmaxf(rm0, __shfl_xor_sync(0xffffffffu, rm0, s));
        rm1 = fmaxf(rm1, __shfl_xor_sync(0xffffffffu, rm1, s));
    }
    if (t == 0) {
        smf[OFF_RMP + r0 * 2 + hf] = rm0;
        smf[OFF_RMP + r1 * 2 + hf] = rm1;
    }

    // ---- LePE precompute (overlaps the softmax barrier): 49x32 fp32 ----
    for (int idx = tid; idx < 49 * 16; idx += 256) {
        int row = idx >> 4, dp = idx & 15;
        int qi = row / 7, qj = row - 7 * (row / 7);
        int c = cbase + 2 * dp;
        float l0 = b_lepe[c], l1 = b_lepe[c + 1];
        #pragma unroll
        for (int di = -1; di <= 1; di++) {
            int yy = qi + di;
            if (yy < 0 || yy >= 7) continue;
            #pragma unroll
            for (int dj = -1; dj <= 1; dj++) {
                int xx = qj + dj;
                if (xx < 0 || xx >= 7) continue;
                int key = yy * 35 + 14 + xx;
                float wv0 = w_lepe[((di + 1) * 3 + dj + 1) * Cc + c];
                float wv1 = w_lepe[((di + 1) * 3 + dj + 1) * Cc + c + 1];
                __half2 vv = *(const __half2*)(Vh + key * 40 + 2 * dp);
                float2 vf = __half22float2(vv);
                l0 = fmaf(wv0, vf.x, l0);
                l1 = fmaf(wv1, vf.y, l1);
            }
        }
        *(float2*)(smf + OFF_LEP + row * 32 + 2 * dp) = make_float2(l0, l1);
    }
    __syncthreads();   // (2) RMP + LEPE ready

    float m0 = fmaxf(smf[OFF_RMP + r0 * 2], smf[OFF_RMP + r0 * 2 + 1]);
    float m1 = fmaxf(smf[OFF_RMP + r1 * 2], smf[OFF_RMP + r1 * 2 + 1]);

    // exp in registers -> half2 A-fragments for PV
    unsigned ah[16], bh[16];
    float s0 = 0.f, s1 = 0.f;
    #pragma unroll
    for (int nt = 0; nt < 16; nt++) {
        int c0 = hf * 128 + nt * 8 + 2 * t;
        float e0 = (c0     < 245) ? __expf(acc[nt][0] - m0) : 0.f;
        float e1 = (c0 + 1 < 245) ? __expf(acc[nt][1] - m0) : 0.f;
        float e2 = (c0     < 245) ? __expf(acc[nt][2] - m1) : 0.f;
        float e3 = (c0 + 1 < 245) ? __expf(acc[nt][3] - m1) : 0.f;
        s0 += e0 + e1; s1 += e2 + e3;
        __half2 p01 = __floats2half2_rn(e0, e1);
        __half2 p23 = __floats2half2_rn(e2, e3);
        ah[nt] = *(unsigned*)&p01;
        bh[nt] = *(unsigned*)&p23;
    }
    #pragma unroll
    for (int s = 1; s <= 2; s <<= 1) {
        s0 += __shfl_xor_sync(0xffffffffu, s0, s);
        s1 += __shfl_xor_sync(0xffffffffu, s1, s);
    }
    if (t == 0) {
        smf[OFF_RSP + r0 * 2 + hf] = s0;
        smf[OFF_RSP + r1 * 2 + hf] = s1;
    }

    // ================= P @ V: A from registers, B = ldsm.trans(V) ===========
    const int vky  = (lane & 7) + (((lane >> 3) & 1) << 3);
    const int vdim = (lane >> 4) << 3;
    float pa[4][4];
    #pragma unroll
    for (int nt = 0; nt < 4; nt++)
        #pragma unroll
        for (int e = 0; e < 4; e++) pa[nt][e] = 0.f;

    #pragma unroll
    for (int ks = 0; ks < 8; ks++) {
        const __half* vp = Vh + (hf * 128 + ks * 16 + vky) * 40;
        unsigned bv0[4], bv1[4];
        ldsm_x4t(bv0, vp + vdim);        // dims 0..15
        ldsm_x4t(bv1, vp + 16 + vdim);   // dims 16..31
        unsigned a0 = ah[2 * ks], a1 = bh[2 * ks], a2 = ah[2 * ks + 1], a3 = bh[2 * ks + 1];
        mma_f16(pa[0], a0, a1, a2, a3, bv0[0], bv0[1]);
        mma_f16(pa[1], a0, a1, a2, a3, bv0[2], bv0[3]);
        mma_f16(pa[2], a0, a1, a2, a3, bv1[0], bv1[1]);
        mma_f16(pa[3], a0, a1, a2, a3, bv1[2], bv1[3]);
    }

    // pair reduction: upper half-warps store, lower adds
    if (hf == 1) {
        float4* red = (float4*)(smf + OFF_RED + mt * 640 + lane * 20);
        #pragma unroll
        for (int nt = 0; nt < 4; nt++)
            red[nt] = make_float4(pa[nt][0], pa[nt][1], pa[nt][2], pa[nt][3]);
    }
    __syncthreads();   // (3) RED + RSP ready

    // ================= epilogue (lower warps) =================
    if (hf == 0) {
        const float4* red = (const float4*)(smf + OFF_RED + mt * 640 + lane * 20);
        #pragma unroll
        for (int nt = 0; nt < 4; nt++) {
            float4 rr = red[nt];
            pa[nt][0] += rr.x; pa[nt][1] += rr.y; pa[nt][2] += rr.z; pa[nt][3] += rr.w;
        }
        float inv0 = 1.0f / (smf[OFF_RSP + r0 * 2] + smf[OFF_RSP + r0 * 2 + 1]);
        float inv1 = 1.0f / (smf[OFF_RSP + r1 * 2] + smf[OFF_RSP + r1 * 2 + 1]);

        #pragma unroll
        for (int half = 0; half < 2; half++) {
            int row = half ? r1 : r0;
            if (row >= 49) continue;
            float inv = half ? inv1 : inv0;
            int qi = row / 7, qj = row - 7 * (row / 7);
            int pix = (ph * 7 + qi) * Wd + pw * 7 + qj;
            float* op = out + (size_t)b * plane + (size_t)pix * Cc + cbase;
            #pragma unroll
            for (int nt = 0; nt < 4; nt++) {
                int d0 = nt * 8 + 2 * t;
                float2 lep = *(const float2*)(smf + OFF_LEP + row * 32 + d0);
                float o0 = pa[nt][half * 2 + 0] * inv + lep.x;
                float o1 = pa[nt][half * 2 + 1] * inv + lep.y;
                *(float2*)(op + d0) = make_float2(o0, o1);
            }
        }
    }
}

extern "C" void kernel_launch(void* const* d_in, const int* in_sizes, int n_in,
                              void* d_out, int out_size)
{
    const float* qkv    = (const float*)d_in[0];
    const float* w_lepe = (const float*)d_in[1];
    const float* b_lepe = (const float*)d_in[2];
    float* out          = (float*)d_out;

    cudaFuncSetAttribute(lepe_attn_kernel,
                         cudaFuncAttributeMaxDynamicSharedMemorySize, SMEM_BYTES);
    lepe_attn_kernel<<<Bn * 8 * 8 * 4, 256, SMEM_BYTES>>>(qkv, w_lepe, b_lepe, out);
}

// round 8
// speedup vs baseline: 3.3273x; 1.6411x over previous
#include <cuda_runtime.h>
#include <cuda_fp16.h>
#include <cstdint>

// ---------------- problem constants ----------------
#define Bn    32
#define Wd    56
#define Cc    128
// SCALE * log2(e): QK^T logits in log2 domain -> exp2f (1 MUFU, no FMUL)
#define SCALE_L2E (0.17677669529663687f * 1.4426950408889634f)

// M=64 (49 q), N=256 (245 k), K=32 head dim. fp16 operands, fp32 accum.
// 512 threads, 16 warps: warp = (mt = w&3) x (kq = w>>2), kq owns 64 keys.
// ---------------- smem layout (word offsets) ----------------
#define OFF_Q    0          // 64 rows x 40 halves  = 1280 words
#define OFF_K    1280       // 256 rows x 40 halves = 5120
#define OFF_V    6400       // 256 rows x 40 halves = 5120
#define OFF_RMP  11520      // 64 rows x 4 partials
#define OFF_RSP  11776      // 64 rows x 4 partials
#define OFF_RED  12032      // 3 kq x 4 mt x 32 lanes x 16 = 6144
#define OFF_LEP  18176      // 49 x 32 fp32 = 1568
#define SMEM_WORDS 19744
#define SMEM_BYTES (SMEM_WORDS * 4)   // 78,976 B -> 2 CTAs/SM (32 warps)

__device__ __forceinline__ void ldsm_x4(unsigned r[4], const void* p) {
    unsigned a = (unsigned)__cvta_generic_to_shared(p);
    asm volatile("ldmatrix.sync.aligned.m8n8.x4.shared.b16 {%0,%1,%2,%3}, [%4];"
        : "=r"(r[0]), "=r"(r[1]), "=r"(r[2]), "=r"(r[3]) : "r"(a));
}
__device__ __forceinline__ void ldsm_x4t(unsigned r[4], const void* p) {
    unsigned a = (unsigned)__cvta_generic_to_shared(p);
    asm volatile("ldmatrix.sync.aligned.m8n8.x4.trans.shared.b16 {%0,%1,%2,%3}, [%4];"
        : "=r"(r[0]), "=r"(r[1]), "=r"(r[2]), "=r"(r[3]) : "r"(a));
}
__device__ __forceinline__ void mma_f16(float c[4],
                                        unsigned a0, unsigned a1, unsigned a2, unsigned a3,
                                        unsigned b0, unsigned b1) {
    asm volatile(
        "mma.sync.aligned.m16n8k16.row.col.f32.f16.f16.f32 "
        "{%0,%1,%2,%3}, {%4,%5,%6,%7}, {%8,%9}, {%0,%1,%2,%3};"
        : "+f"(c[0]), "+f"(c[1]), "+f"(c[2]), "+f"(c[3])
        : "r"(a0), "r"(a1), "r"(a2), "r"(a3), "r"(b0), "r"(b1));
}

__global__ __launch_bounds__(512, 2)
void lepe_attn_kernel(const float* __restrict__ qkv,
                      const float* __restrict__ w_lepe,
                      const float* __restrict__ b_lepe,
                      float* __restrict__ out)
{
    extern __shared__ float smf[];
    __half* smh = (__half*)smf;

    const int bid = blockIdx.x;
    const int h   = bid & 3;
    const int pw  = (bid >> 2) & 7;
    const int ph  = (bid >> 5) & 7;
    const int b   = bid >> 8;
    const int tid = threadIdx.x;
    const int w   = tid >> 5;
    const int lane = tid & 31;
    const int g   = lane >> 2;
    const int t   = lane & 3;
    const int mt  = w & 3;       // m-tile (16 rows)
    const int kq  = w >> 2;      // key quarter (64 keys)

    const size_t plane = (size_t)Wd * Wd * Cc;
    const float* qg = qkv + (size_t)b * plane;
    const float* kg = qkv + (size_t)Bn * plane     + (size_t)b * plane;
    const float* vg = qkv + (size_t)2 * Bn * plane + (size_t)b * plane;
    const int cbase = h * 32;

    // ================= load phase =================
    __half* Qh = smh + OFF_Q * 2;
    __half* Kh = smh + OFF_K * 2;
    __half* Vh = smh + OFF_V * 2;
    {   // Q: one float4 per thread (64*8 = 512)
        int r  = tid >> 3;
        int dv = (tid & 7) << 2;
        __half2 h01 = __floats2half2_rn(0.f, 0.f), h23 = h01;
        if (r < 49) {
            int qi = r / 7, qj = r - 7 * (r / 7);
            int pix = (ph * 7 + qi) * Wd + pw * 7 + qj;
            float4 v = *(const float4*)(qg + (size_t)pix * Cc + cbase + dv);
            h01 = __floats2half2_rn(v.x * SCALE_L2E, v.y * SCALE_L2E);
            h23 = __floats2half2_rn(v.z * SCALE_L2E, v.w * SCALE_L2E);
        }
        *(uint2*)(Qh + r * 40 + dv) = make_uint2(*(unsigned*)&h01, *(unsigned*)&h23);
    }
    #pragma unroll
    for (int it = 0; it < 4; it++) {
        int idx = tid + it * 512;
        int kk = idx >> 3;
        int dv = (idx & 7) << 2;
        float4 kv = make_float4(0.f, 0.f, 0.f, 0.f);
        float4 vv = make_float4(0.f, 0.f, 0.f, 0.f);
        if (kk < 245) {
            int ky = kk / 35, kx = kk - 35 * (kk / 35);
            int x = pw * 7 + kx - 14;
            int y = ph * 7 + ky;
            if (x >= 0 && x < Wd) {
                size_t gi = (size_t)(y * Wd + x) * Cc + cbase + dv;
                kv = *(const float4*)(kg + gi);
                vv = *(const float4*)(vg + gi);
            }
        }
        __half2 k01 = __floats2half2_rn(kv.x, kv.y), k23 = __floats2half2_rn(kv.z, kv.w);
        __half2 v01 = __floats2half2_rn(vv.x, vv.y), v23 = __floats2half2_rn(vv.z, vv.w);
        *(uint2*)(Kh + kk * 40 + dv) = make_uint2(*(unsigned*)&k01, *(unsigned*)&k23);
        *(uint2*)(Vh + kk * 40 + dv) = make_uint2(*(unsigned*)&v01, *(unsigned*)&v23);
    }
    __syncthreads();   // (1)

    // ================= QK^T: warp = (mt, kq), 16 HMMA =================
    const int arow = lane & 15, acol = (lane >> 4) << 3;
    const int brow = (lane & 7) + ((lane >> 4) << 3);
    const int bcol = ((lane >> 3) & 1) << 3;
    unsigned aq[2][4];
    ldsm_x4(aq[0], Qh + (mt * 16 + arow) * 40 + acol);
    ldsm_x4(aq[1], Qh + (mt * 16 + arow) * 40 + 16 + acol);

    float acc[8][4];
    #pragma unroll
    for (int nt = 0; nt < 8; nt++)
        #pragma unroll
        for (int e = 0; e < 4; e++) acc[nt][e] = 0.f;

    #pragma unroll
    for (int j = 0; j < 4; j++) {
        int n0 = kq * 64 + j * 16;
        #pragma unroll
        for (int ks = 0; ks < 2; ks++) {
            unsigned bk[4];
            ldsm_x4(bk, Kh + (n0 + brow) * 40 + ks * 16 + bcol);
            mma_f16(acc[2 * j],     aq[ks][0], aq[ks][1], aq[ks][2], aq[ks][3], bk[0], bk[1]);
            mma_f16(acc[2 * j + 1], aq[ks][0], aq[ks][1], aq[ks][2], aq[ks][3], bk[2], bk[3]);
        }
    }

    // ================= softmax: quad shuffle + 4-warp combine =================
    const int r0 = mt * 16 + g, r1 = r0 + 8;
    float rm0 = -1e30f, rm1 = -1e30f;
    #pragma unroll
    for (int nt = 0; nt < 8; nt++) {
        rm0 = fmaxf(rm0, fmaxf(acc[nt][0], acc[nt][1]));
        rm1 = fmaxf(rm1, fmaxf(acc[nt][2], acc[nt][3]));
    }
    #pragma unroll
    for (int s = 1; s <= 2; s <<= 1) {
        rm0 = fmaxf(rm0, __shfl_xor_sync(0xffffffffu, rm0, s));
        rm1 = fmaxf(rm1, __shfl_xor_sync(0xffffffffu, rm1, s));
    }
    if (t == 0) {
        smf[OFF_RMP + r0 * 4 + kq] = rm0;
        smf[OFF_RMP + r1 * 4 + kq] = rm1;
    }

    // ---- LePE precompute (overlaps barrier): 49 rows x 16 dim-pairs ----
    for (int idx = tid; idx < 49 * 16; idx += 512) {
        int row = idx >> 4, dp = idx & 15;
        int qi = row / 7, qj = row - 7 * (row / 7);
        int c = cbase + 2 * dp;
        float l0 = b_lepe[c], l1 = b_lepe[c + 1];
        #pragma unroll
        for (int di = -1; di <= 1; di++) {
            int yy = qi + di;
            if (yy < 0 || yy >= 7) continue;
            #pragma unroll
            for (int dj = -1; dj <= 1; dj++) {
                int xx = qj + dj;
                if (xx < 0 || xx >= 7) continue;
                int key = yy * 35 + 14 + xx;
                float wv0 = w_lepe[((di + 1) * 3 + dj + 1) * Cc + c];
                float wv1 = w_lepe[((di + 1) * 3 + dj + 1) * Cc + c + 1];
                float2 vf = __half22float2(*(const __half2*)(Vh + key * 40 + 2 * dp));
                l0 = fmaf(wv0, vf.x, l0);
                l1 = fmaf(wv1, vf.y, l1);
            }
        }
        *(float2*)(smf + OFF_LEP + row * 32 + 2 * dp) = make_float2(l0, l1);
    }
    __syncthreads();   // (2) RMP + LEPE ready

    float m0 = fmaxf(fmaxf(smf[OFF_RMP + r0 * 4 + 0], smf[OFF_RMP + r0 * 4 + 1]),
                     fmaxf(smf[OFF_RMP + r0 * 4 + 2], smf[OFF_RMP + r0 * 4 + 3]));
    float m1 = fmaxf(fmaxf(smf[OFF_RMP + r1 * 4 + 0], smf[OFF_RMP + r1 * 4 + 1]),
                     fmaxf(smf[OFF_RMP + r1 * 4 + 2], smf[OFF_RMP + r1 * 4 + 3]));

    // exp2 in registers -> half2 A-fragments for PV
    unsigned ah[8], bh[8];
    float s0 = 0.f, s1 = 0.f;
    #pragma unroll
    for (int nt = 0; nt < 8; nt++) {
        int c0 = kq * 64 + nt * 8 + 2 * t;
        float e0 = (c0     < 245) ? exp2f(acc[nt][0] - m0) : 0.f;
        float e1 = (c0 + 1 < 245) ? exp2f(acc[nt][1] - m0) : 0.f;
        float e2 = (c0     < 245) ? exp2f(acc[nt][2] - m1) : 0.f;
        float e3 = (c0 + 1 < 245) ? exp2f(acc[nt][3] - m1) : 0.f;
        s0 += e0 + e1; s1 += e2 + e3;
        __half2 p01 = __floats2half2_rn(e0, e1);
        __half2 p23 = __floats2half2_rn(e2, e3);
        ah[nt] = *(unsigned*)&p01;
        bh[nt] = *(unsigned*)&p23;
    }
    #pragma unroll
    for (int s = 1; s <= 2; s <<= 1) {
        s0 += __shfl_xor_sync(0xffffffffu, s0, s);
        s1 += __shfl_xor_sync(0xffffffffu, s1, s);
    }
    if (t == 0) {
        smf[OFF_RSP + r0 * 4 + kq] = s0;
        smf[OFF_RSP + r1 * 4 + kq] = s1;
    }

    // ================= P @ V: A from registers, B = ldsm.trans(V) ===========
    const int vky  = (lane & 7) + (((lane >> 3) & 1) << 3);
    const int vdim = (lane >> 4) << 3;
    float pa[4][4];
    #pragma unroll
    for (int nt = 0; nt < 4; nt++)
        #pragma unroll
        for (int e = 0; e < 4; e++) pa[nt][e] = 0.f;

    #pragma unroll
    for (int ks = 0; ks < 4; ks++) {
        const __half* vp = Vh + (kq * 64 + ks * 16 + vky) * 40;
        unsigned bv0[4], bv1[4];
        ldsm_x4t(bv0, vp + vdim);        // dims 0..15
        ldsm_x4t(bv1, vp + 16 + vdim);   // dims 16..31
        unsigned a0 = ah[2 * ks], a1 = bh[2 * ks], a2 = ah[2 * ks + 1], a3 = bh[2 * ks + 1];
        mma_f16(pa[0], a0, a1, a2, a3, bv0[0], bv0[1]);
        mma_f16(pa[1], a0, a1, a2, a3, bv0[2], bv0[3]);
        mma_f16(pa[2], a0, a1, a2, a3, bv1[0], bv1[1]);
        mma_f16(pa[3], a0, a1, a2, a3, bv1[2], bv1[3]);
    }

    // kq 1..3 store partials; kq 0 reduces after barrier
    if (kq > 0) {
        float4* red = (float4*)(smf + OFF_RED + ((kq - 1) * 4 + mt) * 512 + lane * 16);
        #pragma unroll
        for (int nt = 0; nt < 4; nt++)
            red[nt] = make_float4(pa[nt][0], pa[nt][1], pa[nt][2], pa[nt][3]);
    }
    __syncthreads();   // (3) RED + RSP ready

    // ================= epilogue (kq == 0 warps) =================
    if (kq == 0) {
        #pragma unroll
        for (int q = 0; q < 3; q++) {
            const float4* red = (const float4*)(smf + OFF_RED + (q * 4 + mt) * 512 + lane * 16);
            #pragma unroll
            for (int nt = 0; nt < 4; nt++) {
                float4 rr = red[nt];
                pa[nt][0] += rr.x; pa[nt][1] += rr.y; pa[nt][2] += rr.z; pa[nt][3] += rr.w;
            }
        }
        float inv0 = 1.0f / (smf[OFF_RSP + r0 * 4] + smf[OFF_RSP + r0 * 4 + 1]
                           + smf[OFF_RSP + r0 * 4 + 2] + smf[OFF_RSP + r0 * 4 + 3]);
        float inv1 = 1.0f / (smf[OFF_RSP + r1 * 4] + smf[OFF_RSP + r1 * 4 + 1]
                           + smf[OFF_RSP + r1 * 4 + 2] + smf[OFF_RSP + r1 * 4 + 3]);

        #pragma unroll
        for (int half = 0; half < 2; half++) {
            int row = half ? r1 : r0;
            if (row >= 49) continue;
            float inv = half ? inv1 : inv0;
            int qi = row / 7, qj = row - 7 * (row / 7);
            int pix = (ph * 7 + qi) * Wd + pw * 7 + qj;
            float* op = out + (size_t)b * plane + (size_t)pix * Cc + cbase;
            #pragma unroll
            for (int nt = 0; nt < 4; nt++) {
                int d0 = nt * 8 + 2 * t;
                float2 lep = *(const float2*)(smf + OFF_LEP + row * 32 + d0);
                float o0 = pa[nt][half * 2 + 0] * inv + lep.x;
                float o1 = pa[nt][half * 2 + 1] * inv + lep.y;
                *(float2*)(op + d0) = make_float2(o0, o1);
            }
        }
    }
}

extern "C" void kernel_launch(void* const* d_in, const int* in_sizes, int n_in,
                              void* d_out, int out_size)
{
    const float* qkv    = (const float*)d_in[0];
    const float* w_lepe = (const float*)d_in[1];
    const float* b_lepe = (const float*)d_in[2];
    float* out          = (float*)d_out;

    cudaFuncSetAttribute(lepe_attn_kernel,
                         cudaFuncAttributeMaxDynamicSharedMemorySize, SMEM_BYTES);
    lepe_attn_kernel<<<Bn * 8 * 8 * 4, 512, SMEM_BYTES>>>(qkv, w_lepe, b_lepe, out);
}

// round 9
// speedup vs baseline: 4.2494x; 1.2771x over previous
#include <cuda_runtime.h>
#include <cuda_fp16.h>
#include <cstdint>

// ---------------- problem constants ----------------
#define Bn    32
#define Wd    56
#define Cc    128
// SCALE * log2(e): logits in log2 domain -> exp2f
#define SCALE_L2E (0.17677669529663687f * 1.4426950408889634f)

// M=64 (49 q), N=256 (245 k), K=32. fp16 operands, fp32 accum.
// 512 threads, 16 warps: warp = (mt = w&3) x (kq = w>>2); kq owns 64 keys.
// ---------------- smem layout (word offsets) ----------------
#define OFF_Q    0          // 64 x 40 halves   = 1280 words
#define OFF_K    1280       // 256 x 40 halves  = 5120
#define OFF_V    6400       // 256 x 40 halves  = 5120
#define OFF_RMP  11520      // 64 x 4
#define OFF_RSP  11776      // 64 x 4
#define OFF_RED  12032      // 3 x 4 x 2 x 128 words (fp16 partials) = 3072
#define OFF_PVT  15104      // padded 9x9x32 halves = 1296 words
#define OFF_LEP  16400      // 49 x 32 fp32 = 1568
#define SMEM_WORDS 17968
#define SMEM_BYTES (SMEM_WORDS * 4)   // 71,872 B -> 2 CTAs/SM (reg-capped anyway)

__device__ __forceinline__ void ldsm_x4(unsigned r[4], const void* p) {
    unsigned a = (unsigned)__cvta_generic_to_shared(p);
    asm volatile("ldmatrix.sync.aligned.m8n8.x4.shared.b16 {%0,%1,%2,%3}, [%4];"
        : "=r"(r[0]), "=r"(r[1]), "=r"(r[2]), "=r"(r[3]) : "r"(a));
}
__device__ __forceinline__ void ldsm_x4t(unsigned r[4], const void* p) {
    unsigned a = (unsigned)__cvta_generic_to_shared(p);
    asm volatile("ldmatrix.sync.aligned.m8n8.x4.trans.shared.b16 {%0,%1,%2,%3}, [%4];"
        : "=r"(r[0]), "=r"(r[1]), "=r"(r[2]), "=r"(r[3]) : "r"(a));
}
__device__ __forceinline__ void mma_f16(float c[4],
                                        unsigned a0, unsigned a1, unsigned a2, unsigned a3,
                                        unsigned b0, unsigned b1) {
    asm volatile(
        "mma.sync.aligned.m16n8k16.row.col.f32.f16.f16.f32 "
        "{%0,%1,%2,%3}, {%4,%5,%6,%7}, {%8,%9}, {%0,%1,%2,%3};"
        : "+f"(c[0]), "+f"(c[1]), "+f"(c[2]), "+f"(c[3])
        : "r"(a0), "r"(a1), "r"(a2), "r"(a3), "r"(b0), "r"(b1));
}
__device__ __forceinline__ unsigned pack_h2(float a, float b) {
    __half2 h = __floats2half2_rn(a, b);
    return *(unsigned*)&h;
}

__global__ __launch_bounds__(512, 2)
void lepe_attn_kernel(const float* __restrict__ qkv,
                      const float* __restrict__ w_lepe,
                      const float* __restrict__ b_lepe,
                      float* __restrict__ out)
{
    extern __shared__ float smf[];
    __half* smh = (__half*)smf;

    const int bid = blockIdx.x;
    const int h   = bid & 3;
    const int pw  = (bid >> 2) & 7;
    const int ph  = (bid >> 5) & 7;
    const int b   = bid >> 8;
    const int tid = threadIdx.x;
    const int w   = tid >> 5;
    const int lane = tid & 31;
    const int g   = lane >> 2;
    const int t   = lane & 3;
    const int mt  = w & 3;
    const int kq  = w >> 2;

    const size_t plane = (size_t)Wd * Wd * Cc;
    const float* qg = qkv + (size_t)b * plane;
    const float* kg = qkv + (size_t)Bn * plane     + (size_t)b * plane;
    const float* vg = qkv + (size_t)2 * Bn * plane + (size_t)b * plane;
    const int cbase = h * 32;

    // ================= load phase =================
    __half* Qh = smh + OFF_Q * 2;
    __half* Kh = smh + OFF_K * 2;
    __half* Vh = smh + OFF_V * 2;
    {   // Q: one float4 per thread (64 rows x 8 chunks = 512)
        int r  = tid >> 3;
        int dv = (tid & 7) << 2;
        __half2 h01 = __floats2half2_rn(0.f, 0.f), h23 = h01;
        if (r < 49) {
            int qi = r / 7, qj = r - 7 * (r / 7);
            int pix = (ph * 7 + qi) * Wd + pw * 7 + qj;
            float4 v = *(const float4*)(qg + (size_t)pix * Cc + cbase + dv);
            h01 = __floats2half2_rn(v.x * SCALE_L2E, v.y * SCALE_L2E);
            h23 = __floats2half2_rn(v.z * SCALE_L2E, v.w * SCALE_L2E);
        }
        *(uint2*)(Qh + r * 40 + dv) = make_uint2(*(unsigned*)&h01, *(unsigned*)&h23);
    }
    // K/V: (row, 16B chunk) items; 256 rows x 4 chunks = 1024 items, 2 iters.
    #pragma unroll
    for (int it = 0; it < 2; it++) {
        int idx = tid + it * 512;
        int kk = idx >> 2;
        int ch = (idx & 3) << 3;     // float/half chunk base: 0,8,16,24
        float4 ka = make_float4(0.f, 0.f, 0.f, 0.f), kb = ka, va = ka, vb = ka;
        if (kk < 245) {
            int ky = kk / 35, kx = kk - 35 * (kk / 35);
            int x = pw * 7 + kx - 14;
            int y = ph * 7 + ky;
            if (x >= 0 && x < Wd) {
                size_t gi = (size_t)(y * Wd + x) * Cc + cbase + ch;
                ka = *(const float4*)(kg + gi);
                kb = *(const float4*)(kg + gi + 4);
                va = *(const float4*)(vg + gi);
                vb = *(const float4*)(vg + gi + 4);
            }
        }
        uint4 ks = make_uint4(pack_h2(ka.x, ka.y), pack_h2(ka.z, ka.w),
                              pack_h2(kb.x, kb.y), pack_h2(kb.z, kb.w));
        uint4 vs = make_uint4(pack_h2(va.x, va.y), pack_h2(va.z, va.w),
                              pack_h2(vb.x, vb.y), pack_h2(vb.z, vb.w));
        *(uint4*)(Kh + kk * 40 + ch) = ks;
        *(uint4*)(Vh + kk * 40 + ch) = vs;
    }
    __syncthreads();   // (1)

    // ================= QK^T: warp = (mt, kq), 16 HMMA =================
    const int arow = lane & 15, acol = (lane >> 4) << 3;
    const int brow = (lane & 7) + ((lane >> 4) << 3);
    const int bcol = ((lane >> 3) & 1) << 3;
    unsigned aq[2][4];
    ldsm_x4(aq[0], Qh + (mt * 16 + arow) * 40 + acol);
    ldsm_x4(aq[1], Qh + (mt * 16 + arow) * 40 + 16 + acol);

    float acc[8][4];
    #pragma unroll
    for (int nt = 0; nt < 8; nt++)
        #pragma unroll
        for (int e = 0; e < 4; e++) acc[nt][e] = 0.f;

    #pragma unroll
    for (int j = 0; j < 4; j++) {
        int n0 = kq * 64 + j * 16;
        #pragma unroll
        for (int ks = 0; ks < 2; ks++) {
            unsigned bk[4];
            ldsm_x4(bk, Kh + (n0 + brow) * 40 + ks * 16 + bcol);
            mma_f16(acc[2 * j],     aq[ks][0], aq[ks][1], aq[ks][2], aq[ks][3], bk[0], bk[1]);
            mma_f16(acc[2 * j + 1], aq[ks][0], aq[ks][1], aq[ks][2], aq[ks][3], bk[2], bk[3]);
        }
    }

    // ================= softmax part 1: quad max + partial store ============
    const int r0 = mt * 16 + g, r1 = r0 + 8;
    {
        float rm0 = -1e30f, rm1 = -1e30f;
        #pragma unroll
        for (int nt = 0; nt < 8; nt++) {
            rm0 = fmaxf(rm0, fmaxf(acc[nt][0], acc[nt][1]));
            rm1 = fmaxf(rm1, fmaxf(acc[nt][2], acc[nt][3]));
        }
        #pragma unroll
        for (int s = 1; s <= 2; s <<= 1) {
            rm0 = fmaxf(rm0, __shfl_xor_sync(0xffffffffu, rm0, s));
            rm1 = fmaxf(rm1, __shfl_xor_sync(0xffffffffu, rm1, s));
        }
        if (t == 0) {
            smf[OFF_RMP + r0 * 4 + kq] = rm0;
            smf[OFF_RMP + r1 * 4 + kq] = rm1;
        }
    }

    // ---- build zero-padded 9x9x32 center-V tile (overlaps barrier) ----
    // pvt[(y,x)] = V[(y-1)*35+14+(x-1)] for y,x in [1,7], else 0
    for (int idx = tid; idx < 81 * 16; idx += 512) {
        int p  = idx >> 4;           // 0..80
        int dp = idx & 15;           // dim pair
        int y = p / 9, x = p - 9 * (p / 9);
        unsigned val = 0u;
        if (y >= 1 && y <= 7 && x >= 1 && x <= 7) {
            int key = (y - 1) * 35 + 13 + x;
            val = *(const unsigned*)(Vh + key * 40 + 2 * dp);
        }
        *((unsigned*)(smf + OFF_PVT) + p * 16 + dp) = val;
    }
    __syncthreads();   // (2) RMP + PVT ready

    float m0 = fmaxf(fmaxf(smf[OFF_RMP + r0 * 4 + 0], smf[OFF_RMP + r0 * 4 + 1]),
                     fmaxf(smf[OFF_RMP + r0 * 4 + 2], smf[OFF_RMP + r0 * 4 + 3]));
    float m1 = fmaxf(fmaxf(smf[OFF_RMP + r1 * 4 + 0], smf[OFF_RMP + r1 * 4 + 1]),
                     fmaxf(smf[OFF_RMP + r1 * 4 + 2], smf[OFF_RMP + r1 * 4 + 3]));

    // exp2 in registers -> half2 A-fragments
    unsigned ah[8], bh[8];
    float s0 = 0.f, s1 = 0.f;
    #pragma unroll
    for (int nt = 0; nt < 8; nt++) {
        int c0 = kq * 64 + nt * 8 + 2 * t;
        float e0 = (c0     < 245) ? exp2f(acc[nt][0] - m0) : 0.f;
        float e1 = (c0 + 1 < 245) ? exp2f(acc[nt][1] - m0) : 0.f;
        float e2 = (c0     < 245) ? exp2f(acc[nt][2] - m1) : 0.f;
        float e3 = (c0 + 1 < 245) ? exp2f(acc[nt][3] - m1) : 0.f;
        s0 += e0 + e1; s1 += e2 + e3;
        ah[nt] = pack_h2(e0, e1);
        bh[nt] = pack_h2(e2, e3);
    }
    #pragma unroll
    for (int s = 1; s <= 2; s <<= 1) {
        s0 += __shfl_xor_sync(0xffffffffu, s0, s);
        s1 += __shfl_xor_sync(0xffffffffu, s1, s);
    }
    if (t == 0) {
        smf[OFF_RSP + r0 * 4 + kq] = s0;
        smf[OFF_RSP + r1 * 4 + kq] = s1;
    }

    // ---- LePE conv from padded tile: unpredicated 9 taps ----
    for (int idx = tid; idx < 49 * 16; idx += 512) {
        int row = idx >> 4, dp = idx & 15;
        int qi = row / 7, qj = row - 7 * (row / 7);
        int c = cbase + 2 * dp;
        float l0 = b_lepe[c], l1 = b_lepe[c + 1];
        const unsigned* pv = (const unsigned*)(smf + OFF_PVT) + (qi * 9 + qj) * 16 + dp;
        #pragma unroll
        for (int tap = 0; tap < 9; tap++) {
            int dy = tap / 3, dx = tap - 3 * (tap / 3);
            float wv0 = w_lepe[tap * Cc + c];
            float wv1 = w_lepe[tap * Cc + c + 1];
            unsigned vbits = pv[(dy * 9 + dx) * 16];
            float2 vf = __half22float2(*(const __half2*)&vbits);
            l0 = fmaf(wv0, vf.x, l0);
            l1 = fmaf(wv1, vf.y, l1);
        }
        *(float2*)(smf + OFF_LEP + row * 32 + 2 * dp) = make_float2(l0, l1);
    }

    // ================= P @ V: A regs, B = ldsm.trans(V) =================
    const int vky  = (lane & 7) + (((lane >> 3) & 1) << 3);
    const int vdim = (lane >> 4) << 3;
    float pa[4][4];
    #pragma unroll
    for (int nt = 0; nt < 4; nt++)
        #pragma unroll
        for (int e = 0; e < 4; e++) pa[nt][e] = 0.f;

    #pragma unroll
    for (int ks = 0; ks < 4; ks++) {
        const __half* vp = Vh + (kq * 64 + ks * 16 + vky) * 40;
        unsigned bv0[4], bv1[4];
        ldsm_x4t(bv0, vp + vdim);
        ldsm_x4t(bv1, vp + 16 + vdim);
        unsigned a0 = ah[2 * ks], a1 = bh[2 * ks], a2 = ah[2 * ks + 1], a3 = bh[2 * ks + 1];
        mma_f16(pa[0], a0, a1, a2, a3, bv0[0], bv0[1]);
        mma_f16(pa[1], a0, a1, a2, a3, bv0[2], bv0[3]);
        mma_f16(pa[2], a0, a1, a2, a3, bv1[0], bv1[1]);
        mma_f16(pa[3], a0, a1, a2, a3, bv1[2], bv1[3]);
    }

    // kq 1..3 store fp16 partials (2x uint4, lane-contiguous)
    if (kq > 0) {
        uint4* red = (uint4*)(smf + OFF_RED) + ((kq - 1) * 4 + mt) * 64;
        red[lane]      = make_uint4(pack_h2(pa[0][0], pa[0][1]), pack_h2(pa[1][0], pa[1][1]),
                                    pack_h2(pa[2][0], pa[2][1]), pack_h2(pa[3][0], pa[3][1]));
        red[32 + lane] = make_uint4(pack_h2(pa[0][2], pa[0][3]), pack_h2(pa[1][2], pa[1][3]),
                                    pack_h2(pa[2][2], pa[2][3]), pack_h2(pa[3][2], pa[3][3]));
    }
    __syncthreads();   // (3) RED + RSP + LEP ready

    // ================= epilogue (kq == 0 warps) =================
    if (kq == 0) {
        #pragma unroll
        for (int q = 0; q < 3; q++) {
            const uint4* red = (const uint4*)(smf + OFF_RED) + (q * 4 + mt) * 64;
            uint4 u0 = red[lane];
            uint4 u1 = red[32 + lane];
            const unsigned* p0 = (const unsigned*)&u0;
            const unsigned* p1 = (const unsigned*)&u1;
            #pragma unroll
            for (int nt = 0; nt < 4; nt++) {
                float2 f0 = __half22float2(*(const __half2*)&p0[nt]);
                float2 f1 = __half22float2(*(const __half2*)&p1[nt]);
                pa[nt][0] += f0.x; pa[nt][1] += f0.y;
                pa[nt][2] += f1.x; pa[nt][3] += f1.y;
            }
        }
        float inv0 = 1.0f / (smf[OFF_RSP + r0 * 4] + smf[OFF_RSP + r0 * 4 + 1]
                           + smf[OFF_RSP + r0 * 4 + 2] + smf[OFF_RSP + r0 * 4 + 3]);
        float inv1 = 1.0f / (smf[OFF_RSP + r1 * 4] + smf[OFF_RSP + r1 * 4 + 1]
                           + smf[OFF_RSP + r1 * 4 + 2] + smf[OFF_RSP + r1 * 4 + 3]);

        #pragma unroll
        for (int half = 0; half < 2; half++) {
            int row = half ? r1 : r0;
            if (row >= 49) continue;
            float inv = half ? inv1 : inv0;
            int qi = row / 7, qj = row - 7 * (row / 7);
            int pix = (ph * 7 + qi) * Wd + pw * 7 + qj;
            float* op = out + (size_t)b * plane + (size_t)pix * Cc + cbase;
            #pragma unroll
            for (int nt = 0; nt < 4; nt++) {
                int d0 = nt * 8 + 2 * t;
                float2 lep = *(const float2*)(smf + OFF_LEP + row * 32 + d0);
                float o0 = pa[nt][half * 2 + 0] * inv + lep.x;
                float o1 = pa[nt][half * 2 + 1] * inv + lep.y;
                *(float2*)(op + d0) = make_float2(o0, o1);
            }
        }
    }
}

extern "C" void kernel_launch(void* const* d_in, const int* in_sizes, int n_in,
                              void* d_out, int out_size)
{
    const float* qkv    = (const float*)d_in[0];
    const float* w_lepe = (const float*)d_in[1];
    const float* b_lepe = (const float*)d_in[2];
    float* out          = (float*)d_out;

    cudaFuncSetAttribute(lepe_attn_kernel,
                         cudaFuncAttributeMaxDynamicSharedMemorySize, SMEM_BYTES);
    lepe_attn_kernel<<<Bn * 8 * 8 * 4, 512, SMEM_BYTES>>>(qkv, w_lepe, b_lepe, out);
}

// round 11
// speedup vs baseline: 4.3235x; 1.0174x over previous
#include <cuda_runtime.h>
#include <cuda_fp16.h>
#include <cstdint>

// ---------------- problem constants ----------------
#define Bn    32
#define Wd    56
#define Cc    128
// SCALE * log2(e): logits in log2 domain -> exp2f
#define SCALE_L2E (0.17677669529663687f * 1.4426950408889634f)

// M=64 (49 q), N=256 (245 k), K=32. fp16 operands, fp32 accum.
// 512 threads, 16 warps: warp = (mt = w&3) x (kq = w>>2); kq owns 64 keys.
// Online softmax: per-kq local max, epilogue rescale. 2 barriers total.
// ---------------- smem layout (word offsets) ----------------
#define OFF_Q    0          // 64 x 40 halves   = 1280 words
#define OFF_K    1280       // 256 x 40 halves  = 5120
#define OFF_V    6400       // 256 x 40 halves  = 5120
#define OFF_RMP  11520      // 64 rows x 4 local maxes
#define OFF_RSP  11776      // 64 rows x 4 local sums
#define OFF_RED  12032      // 3 kq x 4 mt x 2 x 128 words (fp16 partials) = 3072
#define OFF_LEP  15104      // 49 x 32 fp32 = 1568
#define SMEM_WORDS 16672
#define SMEM_BYTES (SMEM_WORDS * 4)   // 66,688 B -> 2 CTAs/SM

__device__ __forceinline__ void ldsm_x4(unsigned r[4], const void* p) {
    unsigned a = (unsigned)__cvta_generic_to_shared(p);
    asm volatile("ldmatrix.sync.aligned.m8n8.x4.shared.b16 {%0,%1,%2,%3}, [%4];"
        : "=r"(r[0]), "=r"(r[1]), "=r"(r[2]), "=r"(r[3]) : "r"(a));
}
__device__ __forceinline__ void ldsm_x4t(unsigned r[4], const void* p) {
    unsigned a = (unsigned)__cvta_generic_to_shared(p);
    asm volatile("ldmatrix.sync.aligned.m8n8.x4.trans.shared.b16 {%0,%1,%2,%3}, [%4];"
        : "=r"(r[0]), "=r"(r[1]), "=r"(r[2]), "=r"(r[3]) : "r"(a));
}
__device__ __forceinline__ void mma_f16(float c[4],
                                        unsigned a0, unsigned a1, unsigned a2, unsigned a3,
                                        unsigned b0, unsigned b1) {
    asm volatile(
        "mma.sync.aligned.m16n8k16.row.col.f32.f16.f16.f32 "
        "{%0,%1,%2,%3}, {%4,%5,%6,%7}, {%8,%9}, {%0,%1,%2,%3};"
        : "+f"(c[0]), "+f"(c[1]), "+f"(c[2]), "+f"(c[3])
        : "r"(a0), "r"(a1), "r"(a2), "r"(a3), "r"(b0), "r"(b1));
}
__device__ __forceinline__ unsigned pack_h2(float a, float b) {
    __half2 h = __floats2half2_rn(a, b);
    return *(unsigned*)&h;
}

__global__ __launch_bounds__(512, 2)
void lepe_attn_kernel(const float* __restrict__ qkv,
                      const float* __restrict__ w_lepe,
                      const float* __restrict__ b_lepe,
                      float* __restrict__ out)
{
    extern __shared__ float smf[];
    __half* smh = (__half*)smf;

    const int bid = blockIdx.x;
    const int h   = bid & 3;
    const int pw  = (bid >> 2) & 7;
    const int ph  = (bid >> 5) & 7;
    const int b   = bid >> 8;
    const int tid = threadIdx.x;
    const int w   = tid >> 5;
    const int lane = tid & 31;
    const int g   = lane >> 2;
    const int t   = lane & 3;
    const int mt  = w & 3;
    const int kq  = w >> 2;

    const size_t plane = (size_t)Wd * Wd * Cc;
    const float* qg = qkv + (size_t)b * plane;
    const float* kg = qkv + (size_t)Bn * plane     + (size_t)b * plane;
    const float* vg = qkv + (size_t)2 * Bn * plane + (size_t)b * plane;
    const int cbase = h * 32;

    // ================= load phase =================
    __half* Qh = smh + OFF_Q * 2;
    __half* Kh = smh + OFF_K * 2;
    __half* Vh = smh + OFF_V * 2;
    {   // Q: one float4 per thread (64 rows x 8 chunks)
        int r  = tid >> 3;
        int dv = (tid & 7) << 2;
        __half2 h01 = __floats2half2_rn(0.f, 0.f), h23 = h01;
        if (r < 49) {
            int qi = r / 7, qj = r - 7 * (r / 7);
            int pix = (ph * 7 + qi) * Wd + pw * 7 + qj;
            float4 v = *(const float4*)(qg + (size_t)pix * Cc + cbase + dv);
            h01 = __floats2half2_rn(v.x * SCALE_L2E, v.y * SCALE_L2E);
            h23 = __floats2half2_rn(v.z * SCALE_L2E, v.w * SCALE_L2E);
        }
        *(uint2*)(Qh + r * 40 + dv) = make_uint2(*(unsigned*)&h01, *(unsigned*)&h23);
    }
    // K/V: 256 rows x 4 chunks(16B smem / 32B gmem). Row-pairing {k, k+4}
    // inside each 8-lane group -> conflict-free STS.128 (stride-80B rows).
    #pragma unroll
    for (int it = 0; it < 2; it++) {
        int idx = tid + it * 512;
        int ws  = idx >> 5;                                  // warp-slot -> 8 rows
        int l   = idx & 31;
        int kk  = ws * 8 + (l >> 3) + (((l >> 2) & 1) << 2); // rows {r, r+4} per group
        int ch  = (l & 3) << 3;                              // float chunk: 0,8,16,24
        float4 ka = make_float4(0.f, 0.f, 0.f, 0.f), kb = ka, va = ka, vb = ka;
        if (kk < 245) {
            int ky = kk / 35, kx = kk - 35 * (kk / 35);
            int x = pw * 7 + kx - 14;
            int y = ph * 7 + ky;
            if (x >= 0 && x < Wd) {
                size_t gi = (size_t)(y * Wd + x) * Cc + cbase + ch;
                ka = *(const float4*)(kg + gi);
                kb = *(const float4*)(kg + gi + 4);
                va = *(const float4*)(vg + gi);
                vb = *(const float4*)(vg + gi + 4);
            }
        }
        uint4 ks = make_uint4(pack_h2(ka.x, ka.y), pack_h2(ka.z, ka.w),
                              pack_h2(kb.x, kb.y), pack_h2(kb.z, kb.w));
        uint4 vs = make_uint4(pack_h2(va.x, va.y), pack_h2(va.z, va.w),
                              pack_h2(vb.x, vb.y), pack_h2(vb.z, vb.w));
        *(uint4*)(Kh + kk * 40 + ch) = ks;
        *(uint4*)(Vh + kk * 40 + ch) = vs;
    }
    __syncthreads();   // (1)

    // ================= QK^T: warp = (mt, kq), 16 HMMA =================
    const int arow = lane & 15, acol = (lane >> 4) << 3;
    const int brow = (lane & 7) + ((lane >> 4) << 3);
    const int bcol = ((lane >> 3) & 1) << 3;
    unsigned aq[2][4];
    ldsm_x4(aq[0], Qh + (mt * 16 + arow) * 40 + acol);
    ldsm_x4(aq[1], Qh + (mt * 16 + arow) * 40 + 16 + acol);

    float acc[8][4];
    #pragma unroll
    for (int nt = 0; nt < 8; nt++)
        #pragma unroll
        for (int e = 0; e < 4; e++) acc[nt][e] = 0.f;

    #pragma unroll
    for (int j = 0; j < 4; j++) {
        int n0 = kq * 64 + j * 16;
        #pragma unroll
        for (int ks = 0; ks < 2; ks++) {
            unsigned bk[4];
            ldsm_x4(bk, Kh + (n0 + brow) * 40 + ks * 16 + bcol);
            mma_f16(acc[2 * j],     aq[ks][0], aq[ks][1], aq[ks][2], aq[ks][3], bk[0], bk[1]);
            mma_f16(acc[2 * j + 1], aq[ks][0], aq[ks][1], aq[ks][2], aq[ks][3], bk[2], bk[3]);
        }
    }

    // ---- LePE conv direct from Vh (independent; fills HMMA drain) ----
    for (int idx = tid; idx < 49 * 16; idx += 512) {
        int row = idx >> 4, dp = idx & 15;
        int qi = row / 7, qj = row - 7 * (row / 7);
        int c = cbase + 2 * dp;
        float l0 = b_lepe[c], l1 = b_lepe[c + 1];
        #pragma unroll
        for (int di = -1; di <= 1; di++) {
            int yy = qi + di;
            if (yy < 0 || yy >= 7) continue;
            #pragma unroll
            for (int dj = -1; dj <= 1; dj++) {
                int xx = qj + dj;
                if (xx < 0 || xx >= 7) continue;
                int key = yy * 35 + 14 + xx;
                float wv0 = w_lepe[((di + 1) * 3 + dj + 1) * Cc + c];
                float wv1 = w_lepe[((di + 1) * 3 + dj + 1) * Cc + c + 1];
                float2 vf = __half22float2(*(const __half2*)(Vh + key * 40 + 2 * dp));
                l0 = fmaf(wv0, vf.x, l0);
                l1 = fmaf(wv1, vf.y, l1);
            }
        }
        *(float2*)(smf + OFF_LEP + row * 32 + 2 * dp) = make_float2(l0, l1);
    }

    // ================= local softmax (no cross-warp max needed) ============
    const int r0 = mt * 16 + g, r1 = r0 + 8;
    float m0 = -1e30f, m1 = -1e30f;
    #pragma unroll
    for (int nt = 0; nt < 8; nt++) {
        m0 = fmaxf(m0, fmaxf(acc[nt][0], acc[nt][1]));
        m1 = fmaxf(m1, fmaxf(acc[nt][2], acc[nt][3]));
    }
    #pragma unroll
    for (int s = 1; s <= 2; s <<= 1) {
        m0 = fmaxf(m0, __shfl_xor_sync(0xffffffffu, m0, s));
        m1 = fmaxf(m1, __shfl_xor_sync(0xffffffffu, m1, s));
    }

    unsigned ah[8], bh[8];
    float s0 = 0.f, s1 = 0.f;
    #pragma unroll
    for (int nt = 0; nt < 8; nt++) {
        int c0 = kq * 64 + nt * 8 + 2 * t;
        float e0 = (c0     < 245) ? exp2f(acc[nt][0] - m0) : 0.f;
        float e1 = (c0 + 1 < 245) ? exp2f(acc[nt][1] - m0) : 0.f;
        float e2 = (c0     < 245) ? exp2f(acc[nt][2] - m1) : 0.f;
        float e3 = (c0 + 1 < 245) ? exp2f(acc[nt][3] - m1) : 0.f;
        s0 += e0 + e1; s1 += e2 + e3;
        ah[nt] = pack_h2(e0, e1);
        bh[nt] = pack_h2(e2, e3);
    }
    #pragma unroll
    for (int s = 1; s <= 2; s <<= 1) {
        s0 += __shfl_xor_sync(0xffffffffu, s0, s);
        s1 += __shfl_xor_sync(0xffffffffu, s1, s);
    }
    if (t == 0) {
        smf[OFF_RMP + r0 * 4 + kq] = m0;
        smf[OFF_RMP + r1 * 4 + kq] = m1;
        smf[OFF_RSP + r0 * 4 + kq] = s0;
        smf[OFF_RSP + r1 * 4 + kq] = s1;
    }

    // ================= P @ V: A regs, B = ldsm.trans(V) =================
    const int vky  = (lane & 7) + (((lane >> 3) & 1) << 3);
    const int vdim = (lane >> 4) << 3;
    float pa[4][4];
    #pragma unroll
    for (int nt = 0; nt < 4; nt++)
        #pragma unroll
        for (int e = 0; e < 4; e++) pa[nt][e] = 0.f;

    #pragma unroll
    for (int ks = 0; ks < 4; ks++) {
        const __half* vp = Vh + (kq * 64 + ks * 16 + vky) * 40;
        unsigned bv0[4], bv1[4];
        ldsm_x4t(bv0, vp + vdim);
        ldsm_x4t(bv1, vp + 16 + vdim);
        unsigned a0 = ah[2 * ks], a1 = bh[2 * ks], a2 = ah[2 * ks + 1], a3 = bh[2 * ks + 1];
        mma_f16(pa[0], a0, a1, a2, a3, bv0[0], bv0[1]);
        mma_f16(pa[1], a0, a1, a2, a3, bv0[2], bv0[3]);
        mma_f16(pa[2], a0, a1, a2, a3, bv1[0], bv1[1]);
        mma_f16(pa[3], a0, a1, a2, a3, bv1[2], bv1[3]);
    }

    // kq 1..3 store fp16 partials (relative to their local max)
    if (kq > 0) {
        uint4* red = (uint4*)(smf + OFF_RED) + ((kq - 1) * 4 + mt) * 64;
        red[lane]      = make_uint4(pack_h2(pa[0][0], pa[0][1]), pack_h2(pa[1][0], pa[1][1]),
                                    pack_h2(pa[2][0], pa[2][1]), pack_h2(pa[3][0], pa[3][1]));
        red[32 + lane] = make_uint4(pack_h2(pa[0][2], pa[0][3]), pack_h2(pa[1][2], pa[1][3]),
                                    pack_h2(pa[2][2], pa[2][3]), pack_h2(pa[3][2], pa[3][3]));
    }
    __syncthreads();   // (2) RED + RMP + RSP + LEP ready

    // ================= epilogue (kq == 0): rescale-combine =================
    if (kq == 0) {
        float4 mv0 = *(const float4*)(smf + OFF_RMP + r0 * 4);
        float4 mv1 = *(const float4*)(smf + OFF_RMP + r1 * 4);
        float4 sv0 = *(const float4*)(smf + OFF_RSP + r0 * 4);
        float4 sv1 = *(const float4*)(smf + OFF_RSP + r1 * 4);
        float mg0 = fmaxf(fmaxf(mv0.x, mv0.y), fmaxf(mv0.z, mv0.w));
        float mg1 = fmaxf(fmaxf(mv1.x, mv1.y), fmaxf(mv1.z, mv1.w));
        float c00 = exp2f(mv0.x - mg0), c01 = exp2f(mv0.y - mg0);
        float c02 = exp2f(mv0.z - mg0), c03 = exp2f(mv0.w - mg0);
        float c10 = exp2f(mv1.x - mg1), c11 = exp2f(mv1.y - mg1);
        float c12 = exp2f(mv1.z - mg1), c13 = exp2f(mv1.w - mg1);
        float den0 = sv0.x * c00 + sv0.y * c01 + sv0.z * c02 + sv0.w * c03;
        float den1 = sv1.x * c10 + sv1.y * c11 + sv1.z * c12 + sv1.w * c13;

        // local partial (kq 0)
        #pragma unroll
        for (int nt = 0; nt < 4; nt++) {
            pa[nt][0] *= c00; pa[nt][1] *= c00;
            pa[nt][2] *= c10; pa[nt][3] *= c10;
        }
        // remote partials (kq 1..3)
        float sc0[3] = {c01, c02, c03};
        float sc1[3] = {c11, c12, c13};
        #pragma unroll
        for (int q = 0; q < 3; q++) {
            const uint4* red = (const uint4*)(smf + OFF_RED) + (q * 4 + mt) * 64;
            uint4 u0 = red[lane];
            uint4 u1 = red[32 + lane];
            const unsigned* p0 = (const unsigned*)&u0;
            const unsigned* p1 = (const unsigned*)&u1;
            #pragma unroll
            for (int nt = 0; nt < 4; nt++) {
                float2 f0 = __half22float2(*(const __half2*)&p0[nt]);
                float2 f1 = __half22float2(*(const __half2*)&p1[nt]);
                pa[nt][0] = fmaf(f0.x, sc0[q], pa[nt][0]);
                pa[nt][1] = fmaf(f0.y, sc0[q], pa[nt][1]);
                pa[nt][2] = fmaf(f1.x, sc1[q], pa[nt][2]);
                pa[nt][3] = fmaf(f1.y, sc1[q], pa[nt][3]);
            }
        }
        float inv0 = 1.0f / den0;
        float inv1 = 1.0f / den1;

        #pragma unroll
        for (int half = 0; half < 2; half++) {
            int row = half ? r1 : r0;
            if (row >= 49) continue;
            float inv = half ? inv1 : inv0;
            int qi = row / 7, qj = row - 7 * (row / 7);
            int pix = (ph * 7 + qi) * Wd + pw * 7 + qj;
            float* op = out + (size_t)b * plane + (size_t)pix * Cc + cbase;
            #pragma unroll
            for (int nt = 0; nt < 4; nt++) {
                int d0 = nt * 8 + 2 * t;
                float2 lep = *(const float2*)(smf + OFF_LEP + row * 32 + d0);
                float o0 = pa[nt][half * 2 + 0] * inv + lep.x;
                float o1 = pa[nt][half * 2 + 1] * inv + lep.y;
                *(float2*)(op + d0) = make_float2(o0, o1);
            }
        }
    }
}

extern "C" void kernel_launch(void* const* d_in, const int* in_sizes, int n_in,
                              void* d_out, int out_size)
{
    const float* qkv    = (const float*)d_in[0];
    const float* w_lepe = (const float*)d_in[1];
    const float* b_lepe = (const float*)d_in[2];
    float* out          = (float*)d_out;

    cudaFuncSetAttribute(lepe_attn_kernel,
                         cudaFuncAttributeMaxDynamicSharedMemorySize, SMEM_BYTES);
    lepe_attn_kernel<<<Bn * 8 * 8 * 4, 512, SMEM_BYTES>>>(qkv, w_lepe, b_lepe, out);
}

// round 12
// speedup vs baseline: 4.4789x; 1.0359x over previous
#include <cuda_runtime.h>
#include <cuda_fp16.h>
#include <cstdint>

// ---------------- problem constants ----------------
#define Bn    32
#define Wd    56
#define Cc    128
// SCALE * log2(e): logits in log2 domain -> exp2f
#define SCALE_L2E (0.17677669529663687f * 1.4426950408889634f)

// M=64 (49 q), N=256 (245 k), K=32. fp16 operands, fp32 accum.
// 512 threads, 16 warps: warp = (mt = w&3) x (kq = w>>2); kq owns 64 keys.
// Online softmax: per-kq local max, epilogue rescale. 2 barriers total.
// ---------------- smem layout (word offsets) ----------------
#define OFF_Q    0          // 64 x 40 halves   = 1280 words
#define OFF_K    1280       // 256 x 40 halves  = 5120
#define OFF_V    6400       // 256 x 40 halves  = 5120
#define OFF_RMP  11520      // 64 rows x 4 local maxes
#define OFF_RSP  11776      // 64 rows x 4 local sums
#define OFF_RED  12032      // 3 kq x 4 mt x 2 x 128 words (fp16 partials) = 3072
#define OFF_LEP  15104      // 49 x 32 fp32 = 1568
#define OFF_WL   16672      // 9 taps x 32 ch fp32 = 288 (this head's lepe weights)
#define OFF_WLB  16960      // 32 ch fp32 bias
#define SMEM_WORDS 16992
#define SMEM_BYTES (SMEM_WORDS * 4)   // 67,968 B -> 2 CTAs/SM

__device__ __forceinline__ void ldsm_x4(unsigned r[4], const void* p) {
    unsigned a = (unsigned)__cvta_generic_to_shared(p);
    asm volatile("ldmatrix.sync.aligned.m8n8.x4.shared.b16 {%0,%1,%2,%3}, [%4];"
        : "=r"(r[0]), "=r"(r[1]), "=r"(r[2]), "=r"(r[3]) : "r"(a));
}
__device__ __forceinline__ void ldsm_x4t(unsigned r[4], const void* p) {
    unsigned a = (unsigned)__cvta_generic_to_shared(p);
    asm volatile("ldmatrix.sync.aligned.m8n8.x4.trans.shared.b16 {%0,%1,%2,%3}, [%4];"
        : "=r"(r[0]), "=r"(r[1]), "=r"(r[2]), "=r"(r[3]) : "r"(a));
}
__device__ __forceinline__ void mma_f16(float c[4],
                                        unsigned a0, unsigned a1, unsigned a2, unsigned a3,
                                        unsigned b0, unsigned b1) {
    asm volatile(
        "mma.sync.aligned.m16n8k16.row.col.f32.f16.f16.f32 "
        "{%0,%1,%2,%3}, {%4,%5,%6,%7}, {%8,%9}, {%0,%1,%2,%3};"
        : "+f"(c[0]), "+f"(c[1]), "+f"(c[2]), "+f"(c[3])
        : "r"(a0), "r"(a1), "r"(a2), "r"(a3), "r"(b0), "r"(b1));
}
__device__ __forceinline__ unsigned pack_h2(float a, float b) {
    __half2 h = __floats2half2_rn(a, b);
    return *(unsigned*)&h;
}

__global__ __launch_bounds__(512, 2)
void lepe_attn_kernel(const float* __restrict__ qkv,
                      const float* __restrict__ w_lepe,
                      const float* __restrict__ b_lepe,
                      float* __restrict__ out)
{
    extern __shared__ float smf[];
    __half* smh = (__half*)smf;

    const int bid = blockIdx.x;
    const int h   = bid & 3;
    const int pw  = (bid >> 2) & 7;
    const int ph  = (bid >> 5) & 7;
    const int b   = bid >> 8;
    const int tid = threadIdx.x;
    const int w   = tid >> 5;
    const int lane = tid & 31;
    const int g   = lane >> 2;
    const int t   = lane & 3;
    const int mt  = w & 3;
    const int kq  = w >> 2;

    const size_t plane = (size_t)Wd * Wd * Cc;
    const float* qg = qkv + (size_t)b * plane;
    const float* kg = qkv + (size_t)Bn * plane     + (size_t)b * plane;
    const float* vg = qkv + (size_t)2 * Bn * plane + (size_t)b * plane;
    const int cbase = h * 32;

    // ================= load phase =================
    __half* Qh = smh + OFF_Q * 2;
    __half* Kh = smh + OFF_K * 2;
    __half* Vh = smh + OFF_V * 2;
    {   // Q: one float4 per thread (64 rows x 8 chunks); lanes 0-7 = one row line
        int r  = tid >> 3;
        int dv = (tid & 7) << 2;
        __half2 h01 = __floats2half2_rn(0.f, 0.f), h23 = h01;
        if (r < 49) {
            int qi = r / 7, qj = r - 7 * (r / 7);
            int pix = (ph * 7 + qi) * Wd + pw * 7 + qj;
            float4 v = *(const float4*)(qg + (size_t)pix * Cc + cbase + dv);
            h01 = __floats2half2_rn(v.x * SCALE_L2E, v.y * SCALE_L2E);
            h23 = __floats2half2_rn(v.z * SCALE_L2E, v.w * SCALE_L2E);
        }
        *(uint2*)(Qh + r * 40 + dv) = make_uint2(*(unsigned*)&h01, *(unsigned*)&h23);
    }
    // lepe weights for this head -> smem (covered by barrier 1)
    if (tid < 288) smf[OFF_WL + tid] = w_lepe[(tid >> 5) * Cc + cbase + (tid & 31)];
    else if (tid >= 480) smf[OFF_WLB + tid - 480] = b_lepe[cbase + tid - 480];

    // K/V: 16B (one float4) per thread per array; lanes 0-7 cover one full
    // 128B gmem row line -> 4 wf per LDG.128 (optimal). 256 rows x 8 chunks.
    #pragma unroll
    for (int it = 0; it < 4; it++) {
        int idx = tid + it * 512;
        int kk = idx >> 3;
        int dv = (idx & 7) << 2;
        float4 kv = make_float4(0.f, 0.f, 0.f, 0.f);
        float4 vv = make_float4(0.f, 0.f, 0.f, 0.f);
        if (kk < 245) {
            int ky = kk / 35, kx = kk - 35 * (kk / 35);
            int x = pw * 7 + kx - 14;
            int y = ph * 7 + ky;
            if (x >= 0 && x < Wd) {
                size_t gi = (size_t)(y * Wd + x) * Cc + cbase + dv;
                kv = *(const float4*)(kg + gi);
                vv = *(const float4*)(vg + gi);
            }
        }
        *(uint2*)(Kh + kk * 40 + dv) = make_uint2(pack_h2(kv.x, kv.y), pack_h2(kv.z, kv.w));
        *(uint2*)(Vh + kk * 40 + dv) = make_uint2(pack_h2(vv.x, vv.y), pack_h2(vv.z, vv.w));
    }
    __syncthreads();   // (1)

    // ================= QK^T: warp = (mt, kq), 16 HMMA =================
    const int arow = lane & 15, acol = (lane >> 4) << 3;
    const int brow = (lane & 7) + ((lane >> 4) << 3);
    const int bcol = ((lane >> 3) & 1) << 3;
    unsigned aq[2][4];
    ldsm_x4(aq[0], Qh + (mt * 16 + arow) * 40 + acol);
    ldsm_x4(aq[1], Qh + (mt * 16 + arow) * 40 + 16 + acol);

    float acc[8][4];
    #pragma unroll
    for (int nt = 0; nt < 8; nt++)
        #pragma unroll
        for (int e = 0; e < 4; e++) acc[nt][e] = 0.f;

    #pragma unroll
    for (int j = 0; j < 4; j++) {
        int n0 = kq * 64 + j * 16;
        #pragma unroll
        for (int ks = 0; ks < 2; ks++) {
            unsigned bk[4];
            ldsm_x4(bk, Kh + (n0 + brow) * 40 + ks * 16 + bcol);
            mma_f16(acc[2 * j],     aq[ks][0], aq[ks][1], aq[ks][2], aq[ks][3], bk[0], bk[1]);
            mma_f16(acc[2 * j + 1], aq[ks][0], aq[ks][1], aq[ks][2], aq[ks][3], bk[2], bk[3]);
        }
    }

    // ---- LePE conv from smem weights + Vh (independent; fills HMMA drain) ----
    for (int idx = tid; idx < 49 * 16; idx += 512) {
        int row = idx >> 4, dp = idx & 15;
        int qi = row / 7, qj = row - 7 * (row / 7);
        float2 bl = *(const float2*)(smf + OFF_WLB + 2 * dp);
        float l0 = bl.x, l1 = bl.y;
        #pragma unroll
        for (int di = -1; di <= 1; di++) {
            int yy = qi + di;
            if (yy < 0 || yy >= 7) continue;
            #pragma unroll
            for (int dj = -1; dj <= 1; dj++) {
                int xx = qj + dj;
                if (xx < 0 || xx >= 7) continue;
                int key = yy * 35 + 14 + xx;
                float2 wv = *(const float2*)(smf + OFF_WL + ((di + 1) * 3 + dj + 1) * 32 + 2 * dp);
                float2 vf = __half22float2(*(const __half2*)(Vh + key * 40 + 2 * dp));
                l0 = fmaf(wv.x, vf.x, l0);
                l1 = fmaf(wv.y, vf.y, l1);
            }
        }
        *(float2*)(smf + OFF_LEP + row * 32 + 2 * dp) = make_float2(l0, l1);
    }

    // ================= local softmax (per-kq max; exact after rescale) =====
    const int r0 = mt * 16 + g, r1 = r0 + 8;
    float m0 = -1e30f, m1 = -1e30f;
    #pragma unroll
    for (int nt = 0; nt < 8; nt++) {
        m0 = fmaxf(m0, fmaxf(acc[nt][0], acc[nt][1]));
        m1 = fmaxf(m1, fmaxf(acc[nt][2], acc[nt][3]));
    }
    #pragma unroll
    for (int s = 1; s <= 2; s <<= 1) {
        m0 = fmaxf(m0, __shfl_xor_sync(0xffffffffu, m0, s));
        m1 = fmaxf(m1, __shfl_xor_sync(0xffffffffu, m1, s));
    }

    unsigned ah[8], bh[8];
    float s0 = 0.f, s1 = 0.f;
    #pragma unroll
    for (int nt = 0; nt < 8; nt++) {
        int c0 = kq * 64 + nt * 8 + 2 * t;
        float e0 = (c0     < 245) ? exp2f(acc[nt][0] - m0) : 0.f;
        float e1 = (c0 + 1 < 245) ? exp2f(acc[nt][1] - m0) : 0.f;
        float e2 = (c0     < 245) ? exp2f(acc[nt][2] - m1) : 0.f;
        float e3 = (c0 + 1 < 245) ? exp2f(acc[nt][3] - m1) : 0.f;
        s0 += e0 + e1; s1 += e2 + e3;
        ah[nt] = pack_h2(e0, e1);
        bh[nt] = pack_h2(e2, e3);
    }
    #pragma unroll
    for (int s = 1; s <= 2; s <<= 1) {
        s0 += __shfl_xor_sync(0xffffffffu, s0, s);
        s1 += __shfl_xor_sync(0xffffffffu, s1, s);
    }
    if (t == 0) {
        smf[OFF_RMP + r0 * 4 + kq] = m0;
        smf[OFF_RMP + r1 * 4 + kq] = m1;
        smf[OFF_RSP + r0 * 4 + kq] = s0;
        smf[OFF_RSP + r1 * 4 + kq] = s1;
    }

    // ================= P @ V: A regs, B = ldsm.trans(V) =================
    const int vky  = (lane & 7) + (((lane >> 3) & 1) << 3);
    const int vdim = (lane >> 4) << 3;
    float pa[4][4];
    #pragma unroll
    for (int nt = 0; nt < 4; nt++)
        #pragma unroll
        for (int e = 0; e < 4; e++) pa[nt][e] = 0.f;

    #pragma unroll
    for (int ks = 0; ks < 4; ks++) {
        const __half* vp = Vh + (kq * 64 + ks * 16 + vky) * 40;
        unsigned bv0[4], bv1[4];
        ldsm_x4t(bv0, vp + vdim);
        ldsm_x4t(bv1, vp + 16 + vdim);
        unsigned a0 = ah[2 * ks], a1 = bh[2 * ks], a2 = ah[2 * ks + 1], a3 = bh[2 * ks + 1];
        mma_f16(pa[0], a0, a1, a2, a3, bv0[0], bv0[1]);
        mma_f16(pa[1], a0, a1, a2, a3, bv0[2], bv0[3]);
        mma_f16(pa[2], a0, a1, a2, a3, bv1[0], bv1[1]);
        mma_f16(pa[3], a0, a1, a2, a3, bv1[2], bv1[3]);
    }

    // kq 1..3 store fp16 partials (relative to their local max)
    if (kq > 0) {
        uint4* red = (uint4*)(smf + OFF_RED) + ((kq - 1) * 4 + mt) * 64;
        red[lane]      = make_uint4(pack_h2(pa[0][0], pa[0][1]), pack_h2(pa[1][0], pa[1][1]),
                                    pack_h2(pa[2][0], pa[2][1]), pack_h2(pa[3][0], pa[3][1]));
        red[32 + lane] = make_uint4(pack_h2(pa[0][2], pa[0][3]), pack_h2(pa[1][2], pa[1][3]),
                                    pack_h2(pa[2][2], pa[2][3]), pack_h2(pa[3][2], pa[3][3]));
    }
    __syncthreads();   // (2) RED + RMP + RSP + LEP ready

    // ================= epilogue (kq == 0): rescale-combine =================
    if (kq == 0) {
        float4 mv0 = *(const float4*)(smf + OFF_RMP + r0 * 4);
        float4 mv1 = *(const float4*)(smf + OFF_RMP + r1 * 4);
        float4 sv0 = *(const float4*)(smf + OFF_RSP + r0 * 4);
        float4 sv1 = *(const float4*)(smf + OFF_RSP + r1 * 4);
        float mg0 = fmaxf(fmaxf(mv0.x, mv0.y), fmaxf(mv0.z, mv0.w));
        float mg1 = fmaxf(fmaxf(mv1.x, mv1.y), fmaxf(mv1.z, mv1.w));
        float c00 = exp2f(mv0.x - mg0), c01 = exp2f(mv0.y - mg0);
        float c02 = exp2f(mv0.z - mg0), c03 = exp2f(mv0.w - mg0);
        float c10 = exp2f(mv1.x - mg1), c11 = exp2f(mv1.y - mg1);
        float c12 = exp2f(mv1.z - mg1), c13 = exp2f(mv1.w - mg1);
        float den0 = sv0.x * c00 + sv0.y * c01 + sv0.z * c02 + sv0.w * c03;
        float den1 = sv1.x * c10 + sv1.y * c11 + sv1.z * c12 + sv1.w * c13;

        #pragma unroll
        for (int nt = 0; nt < 4; nt++) {
            pa[nt][0] *= c00; pa[nt][1] *= c00;
            pa[nt][2] *= c10; pa[nt][3] *= c10;
        }
        float sc0[3] = {c01, c02, c03};
        float sc1[3] = {c11, c12, c13};
        #pragma unroll
        for (int q = 0; q < 3; q++) {
            const uint4* red = (const uint4*)(smf + OFF_RED) + (q * 4 + mt) * 64;
            uint4 u0 = red[lane];
            uint4 u1 = red[32 + lane];
            const unsigned* p0 = (const unsigned*)&u0;
            const unsigned* p1 = (const unsigned*)&u1;
            #pragma unroll
            for (int nt = 0; nt < 4; nt++) {
                float2 f0 = __half22float2(*(const __half2*)&p0[nt]);
                float2 f1 = __half22float2(*(const __half2*)&p1[nt]);
                pa[nt][0] = fmaf(f0.x, sc0[q], pa[nt][0]);
                pa[nt][1] = fmaf(f0.y, sc0[q], pa[nt][1]);
                pa[nt][2] = fmaf(f1.x, sc1[q], pa[nt][2]);
                pa[nt][3] = fmaf(f1.y, sc1[q], pa[nt][3]);
            }
        }
        float inv0 = 1.0f / den0;
        float inv1 = 1.0f / den1;

        #pragma unroll
        for (int half = 0; half < 2; half++) {
            int row = half ? r1 : r0;
            if (row >= 49) continue;
            float inv = half ? inv1 : inv0;
            int qi = row / 7, qj = row - 7 * (row / 7);
            int pix = (ph * 7 + qi) * Wd + pw * 7 + qj;
            float* op = out + (size_t)b * plane + (size_t)pix * Cc + cbase;
            #pragma unroll
            for (int nt = 0; nt < 4; nt++) {
                int d0 = nt * 8 + 2 * t;
                float2 lep = *(const float2*)(smf + OFF_LEP + row * 32 + d0);
                float o0 = pa[nt][half * 2 + 0] * inv + lep.x;
                float o1 = pa[nt][half * 2 + 1] * inv + lep.y;
                *(float2*)(op + d0) = make_float2(o0, o1);
            }
        }
    }
}

extern "C" void kernel_launch(void* const* d_in, const int* in_sizes, int n_in,
                              void* d_out, int out_size)
{
    const float* qkv    = (const float*)d_in[0];
    const float* w_lepe = (const float*)d_in[1];
    const float* b_lepe = (const float*)d_in[2];
    float* out          = (float*)d_out;

    cudaFuncSetAttribute(lepe_attn_kernel,
                         cudaFuncAttributeMaxDynamicSharedMemorySize, SMEM_BYTES);
    lepe_attn_kernel<<<Bn * 8 * 8 * 4, 512, SMEM_BYTES>>>(qkv, w_lepe, b_lepe, out);
}